// round 7
// baseline (speedup 1.0000x reference)
#include <cuda_runtime.h>
#include <cuda_bf16.h>
#include <cstdint>

// Problem constants
#define BB 2
#define NN 2048
#define DD 1024
#define HH 16
#define HKV 4
#define HD 64
#define REP 4
#define MROWS (BB * NN)      // 4096
#define KVD (HKV * HD)       // 256
#define QKVD (DD + 2 * KVD)  // 1536

// ---------------------------------------------------------------------------
// Scratch (static device globals)
// ---------------------------------------------------------------------------
__device__ float g_qkv[MROWS * QKVD];    // packed QKV projections (tf32-rounded)
__device__ float g_o[MROWS * DD];        // attention out (tf32-rounded)
__device__ float g_wqkv[QKVD * DD];      // transposed Wq|Wk|Wv: [n][k], rounded
__device__ float g_wot[DD * DD];         // transposed Wo: [n][k], rounded

// ---------------------------------------------------------------------------
// Helpers
// ---------------------------------------------------------------------------
__device__ __forceinline__ uint32_t f2tf32(float x) {
    uint32_t r;
    asm("cvt.rna.tf32.f32 %0, %1;" : "=r"(r) : "f"(x));
    return r;
}
__device__ __forceinline__ float rnd_tf32(float x) {
    return __uint_as_float(f2tf32(x));
}
__device__ __forceinline__ float ex2(float x) {
    float r;
    asm("ex2.approx.ftz.f32 %0, %1;" : "=f"(r) : "f"(x));
    return r;
}
__device__ __forceinline__ void mma_tf32(float* c, float a0, float a1,
                                         float a2, float a3,
                                         float b0, float b1) {
    asm volatile(
        "mma.sync.aligned.m16n8k8.row.col.f32.tf32.tf32.f32 "
        "{%0,%1,%2,%3}, {%4,%5,%6,%7}, {%8,%9}, {%0,%1,%2,%3};\n"
        : "+f"(c[0]), "+f"(c[1]), "+f"(c[2]), "+f"(c[3])
        : "r"(__float_as_uint(a0)), "r"(__float_as_uint(a1)),
          "r"(__float_as_uint(a2)), "r"(__float_as_uint(a3)),
          "r"(__float_as_uint(b0)), "r"(__float_as_uint(b1)));
}

// ---------------------------------------------------------------------------
// Permuted/swizzled smem layout.
// Per 16-col k-group, logical col c sits at perm position p=(c&3)*4+(c>>2).
// Quad (16B unit) is XOR-swizzled by row: quad_phys = quad_log ^ swz(row).
// Fragment read: one LDS.128 at quad t gives cols {t,t+4,t+8,t+12} of a group
// = (b0,b1) / (a0,a2) for TWO consecutive k8 MMA steps.
// ---------------------------------------------------------------------------
__device__ __forceinline__ int swzf(int r) { return (r ^ (r >> 2)) & 3; }

// store 4 consecutive logical cols (4*f4col + 0..3) of row r
__device__ __forceinline__ void sts_perm(float* base, int pitch, int r,
                                         int f4col, float4 v, bool rnd) {
    if (rnd) {
        v.x = rnd_tf32(v.x); v.y = rnd_tf32(v.y);
        v.z = rnd_tf32(v.z); v.w = rnd_tf32(v.w);
    }
    const int w0 = r * pitch + (f4col >> 2) * 16 + (f4col & 3);
    const int sz = swzf(r);
    base[w0 + ((0 ^ sz) << 2)] = v.x;
    base[w0 + ((1 ^ sz) << 2)] = v.y;
    base[w0 + ((2 ^ sz) << 2)] = v.z;
    base[w0 + ((3 ^ sz) << 2)] = v.w;
}
// store single logical col c of row r
__device__ __forceinline__ void sts_col(float* base, int pitch, int r, int c,
                                        float v) {
    const int cc = c & 15;
    base[r * pitch + (c >> 4) * 16 + (((cc & 3) ^ swzf(r)) << 2) + (cc >> 2)] = v;
}
// fragment read: 16B of group grp, quad t, row r
__device__ __forceinline__ float4 ldf(const float* base, int pitch, int r,
                                      int grp, int t) {
    return *(const float4*)(base + r * pitch + grp * 16 +
                            ((t ^ swzf(r)) << 2));
}

// ---------------------------------------------------------------------------
// Tiled transpose + tf32-round: dst[c][r] = rnd(src[r][c])
// ---------------------------------------------------------------------------
__global__ void transpose_round(const float* __restrict__ src, int R, int C,
                                float* __restrict__ dst) {
    __shared__ float t[32][33];
    const int r0 = blockIdx.y * 32, c0 = blockIdx.x * 32;
    const int tx = threadIdx.x, ty = threadIdx.y;
#pragma unroll
    for (int i = 0; i < 32; i += 8)
        t[ty + i][tx] = src[(size_t)(r0 + ty + i) * C + c0 + tx];
    __syncthreads();
#pragma unroll
    for (int i = 0; i < 32; i += 8)
        dst[(size_t)(c0 + ty + i) * R + r0 + tx] = rnd_tf32(t[tx][ty + i]);
}

// ---------------------------------------------------------------------------
// tf32 GEMM with permuted smem + LDS.128 fragment feed.
// C[M,N] = A[M,K] @ Bt[N,K]^T. CTA tile 128x128, K-stage 32, 8 warps,
// warp tile 32x64. Ping-pong smem, one sync per stage.
// ---------------------------------------------------------------------------
#define GP 48                       // smem pitch (floats) for 32-col stage
#define GBUF (128 * GP)             // 6144 floats per operand buffer
#define GEMM_SMEM (4 * GBUF * 4)    // A0,B0,A1,B1 = 98304 bytes

template <bool RA, bool RB, bool RC>
__global__ __launch_bounds__(256, 2) void gemm_perm(
    int M, int N, int K,
    const float* __restrict__ A, const float* __restrict__ Bt,
    float* __restrict__ C)
{
    extern __shared__ float sm[];
    float* Ab[2] = { sm, sm + 2 * GBUF };
    float* Bb[2] = { sm + GBUF, sm + 3 * GBUF };

    const int tid  = threadIdx.x;
    const int lane = tid & 31;
    const int w    = tid >> 5;
    const int g    = lane >> 2;
    const int t    = lane & 3;
    const int wm   = (w & 3) * 32;
    const int wn   = (w >> 2) * 64;
    const int bm   = blockIdx.y * 128;
    const int bn   = blockIdx.x * 128;
    const int NS   = K / 32;

    const int lrow   = tid >> 3;    // + i*32
    const int lf4    = tid & 7;

    float acc[2][8][4];
#pragma unroll
    for (int mt = 0; mt < 2; mt++)
#pragma unroll
        for (int nt = 0; nt < 8; nt++)
#pragma unroll
            for (int j = 0; j < 4; j++) acc[mt][nt][j] = 0.f;

    float4 ar[4], br[4];
    auto ldgA = [&](int s) {
#pragma unroll
        for (int i = 0; i < 4; i++)
            ar[i] = *(const float4*)(A + (size_t)(bm + lrow + i * 32) * K +
                                     s * 32 + lf4 * 4);
    };
    auto ldgB = [&](int s) {
#pragma unroll
        for (int i = 0; i < 4; i++)
            br[i] = *(const float4*)(Bt + (size_t)(bn + lrow + i * 32) * K +
                                     s * 32 + lf4 * 4);
    };
    auto stsA = [&](int buf) {
#pragma unroll
        for (int i = 0; i < 4; i++)
            sts_perm(Ab[buf], GP, lrow + i * 32, lf4, ar[i], RA);
    };
    auto stsB = [&](int buf) {
#pragma unroll
        for (int i = 0; i < 4; i++)
            sts_perm(Bb[buf], GP, lrow + i * 32, lf4, br[i], RB);
    };
    auto compute_half = [&](const float* Ac, const float* Bc, int kp) {
        float4 alo[2], ahi[2];
#pragma unroll
        for (int mt = 0; mt < 2; mt++) {
            const int rlo = wm + mt * 16 + g;
            alo[mt] = ldf(Ac, GP, rlo, kp, t);
            ahi[mt] = ldf(Ac, GP, rlo + 8, kp, t);
        }
#pragma unroll
        for (int nt = 0; nt < 8; nt++) {
            const float4 bv = ldf(Bc, GP, wn + nt * 8 + g, kp, t);
#pragma unroll
            for (int mt = 0; mt < 2; mt++) {
                mma_tf32(acc[mt][nt], alo[mt].x, ahi[mt].x, alo[mt].y,
                         ahi[mt].y, bv.x, bv.y);
                mma_tf32(acc[mt][nt], alo[mt].z, ahi[mt].z, alo[mt].w,
                         ahi[mt].w, bv.z, bv.w);
            }
        }
    };

    ldgA(0); ldgB(0);
    stsA(0); stsB(0);
    __syncthreads();

    for (int s = 0; s < NS; s++) {
        const int cur = s & 1, nxt = cur ^ 1;
        const bool more = (s + 1 < NS);
        if (more) ldgA(s + 1);
        compute_half(Ab[cur], Bb[cur], 0);
        if (more) { stsA(nxt); ldgB(s + 1); }
        compute_half(Ab[cur], Bb[cur], 1);
        if (more) stsB(nxt);
        __syncthreads();
    }

#pragma unroll
    for (int mt = 0; mt < 2; mt++)
#pragma unroll
        for (int nt = 0; nt < 8; nt++) {
            const int row = bm + wm + mt * 16 + g;
            const int col = bn + wn + nt * 8 + 2 * t;
            float v0 = acc[mt][nt][0], v1 = acc[mt][nt][1];
            float v2 = acc[mt][nt][2], v3 = acc[mt][nt][3];
            if (RC) {
                v0 = rnd_tf32(v0); v1 = rnd_tf32(v1);
                v2 = rnd_tf32(v2); v3 = rnd_tf32(v3);
            }
            *(float2*)(C + (size_t)row * N + col) = make_float2(v0, v1);
            *(float2*)(C + (size_t)(row + 8) * N + col) = make_float2(v2, v3);
        }
}

// ---------------------------------------------------------------------------
// Flash attention, permuted smem + LDS.128 fragment feed everywhere.
// Br=64 (4 warps x 16 rows), Bc=64. V stored TRANSPOSED [hd][kv].
// ---------------------------------------------------------------------------
#define KP 80                        // attention smem pitch (floats)
#define TBUF (64 * KP)               // 5120 floats
#define NT (NN / 64)
#define ATT_SMEM (5 * TBUF * 4)      // K0,K1,V0,V1,Ps = 102400 bytes

__global__ __launch_bounds__(128, 2) void attn_perm(
    const float* __restrict__ QKV, float* __restrict__ O)
{
    extern __shared__ float sm[];
    float* Kb[2] = { sm, sm + TBUF };
    float* Vb[2] = { sm + 2 * TBUF, sm + 3 * TBUF };
    float* Ps = sm + 4 * TBUF;

    const int tid  = threadIdx.x;
    const int lane = tid & 31;
    const int w    = tid >> 5;
    const int g    = lane >> 2;
    const int t    = lane & 3;
    const int b    = blockIdx.z;
    const int h    = blockIdx.y;
    const int q0   = blockIdx.x * 64;
    const int kvh  = h >> 2;
    const float SCALE = 0.125f * 1.4426950408889634f;

    const float* kbase = QKV + (size_t)b * NN * QKVD + DD + kvh * HD;
    const float* vbase = QKV + (size_t)b * NN * QKVD + DD + KVD + kvh * HD;

    const int lkv = tid >> 4;        // + i*8 : kv row
    const int lf4 = tid & 15;        // f4 col within 64-float row

    float4 stg[8];
    auto ldgK = [&](int kt) {
#pragma unroll
        for (int i = 0; i < 8; i++)
            stg[i] = *(const float4*)(kbase +
                (size_t)(kt * 64 + lkv + i * 8) * QKVD + lf4 * 4);
    };
    auto stsK = [&](int buf) {
#pragma unroll
        for (int i = 0; i < 8; i++)
            sts_perm(Kb[buf], KP, lkv + i * 8, lf4, stg[i], false);
    };
    auto ldgV = [&](int kt) {
#pragma unroll
        for (int i = 0; i < 8; i++)
            stg[i] = *(const float4*)(vbase +
                (size_t)(kt * 64 + lkv + i * 8) * QKVD + lf4 * 4);
    };
    auto stsV = [&](int buf) {      // transposed: Vt[hd][kv]
        const int hd4 = lf4 * 4;
#pragma unroll
        for (int i = 0; i < 8; i++) {
            const int kv = lkv + i * 8;
            sts_col(Vb[buf], KP, hd4 + 0, kv, stg[i].x);
            sts_col(Vb[buf], KP, hd4 + 1, kv, stg[i].y);
            sts_col(Vb[buf], KP, hd4 + 2, kv, stg[i].z);
            sts_col(Vb[buf], KP, hd4 + 3, kv, stg[i].w);
        }
    };

    // Q fragments (registers, whole kernel)
    float qa[8][4];
    {
        const float* qb = QKV + (size_t)(b * NN + q0 + w * 16) * QKVD + h * HD;
#pragma unroll
        for (int kf = 0; kf < 8; kf++) {
            qa[kf][0] = rnd_tf32(qb[(size_t)g * QKVD + kf * 8 + t] * SCALE);
            qa[kf][1] = rnd_tf32(qb[(size_t)(g + 8) * QKVD + kf * 8 + t] * SCALE);
            qa[kf][2] = rnd_tf32(qb[(size_t)g * QKVD + kf * 8 + t + 4] * SCALE);
            qa[kf][3] = rnd_tf32(qb[(size_t)(g + 8) * QKVD + kf * 8 + t + 4] * SCALE);
        }
    }

    float o[8][4];
#pragma unroll
    for (int nt = 0; nt < 8; nt++)
#pragma unroll
        for (int j = 0; j < 4; j++) o[nt][j] = 0.f;
    float m0 = -1e30f, m1 = -1e30f, l0 = 0.f, l1 = 0.f;

    // prologue: K must be staged BEFORE ldgV clobbers the stg registers
    // (this exact clobber was the Round-6 correctness bug)
    ldgK(0); stsK(0);
    ldgV(0); stsV(0);
    __syncthreads();

    const int prow0 = w * 16 + g, prow1 = prow0 + 8;

    for (int kt = 0; kt < NT; kt++) {
        const int cur = kt & 1, nxt = cur ^ 1;
        const bool more = (kt + 1 < NT);

        if (more) ldgK(kt + 1);

        // S = Q @ K^T  (16 x 64)
        float s[8][4];
#pragma unroll
        for (int nt = 0; nt < 8; nt++)
#pragma unroll
            for (int j = 0; j < 4; j++) s[nt][j] = 0.f;
#pragma unroll
        for (int kp = 0; kp < 4; kp++) {
#pragma unroll
            for (int nt = 0; nt < 8; nt++) {
                const float4 bv = ldf(Kb[cur], KP, nt * 8 + g, kp, t);
                mma_tf32(s[nt], qa[2 * kp][0], qa[2 * kp][1], qa[2 * kp][2],
                         qa[2 * kp][3], bv.x, bv.y);
                mma_tf32(s[nt], qa[2 * kp + 1][0], qa[2 * kp + 1][1],
                         qa[2 * kp + 1][2], qa[2 * kp + 1][3], bv.z, bv.w);
            }
        }
        if (more) stsK(nxt);

        // online softmax (rows g and g+8 of this warp's 16)
        float mx0 = -1e30f, mx1 = -1e30f;
#pragma unroll
        for (int nt = 0; nt < 8; nt++) {
            mx0 = fmaxf(mx0, fmaxf(s[nt][0], s[nt][1]));
            mx1 = fmaxf(mx1, fmaxf(s[nt][2], s[nt][3]));
        }
        mx0 = fmaxf(mx0, __shfl_xor_sync(0xffffffffu, mx0, 1));
        mx0 = fmaxf(mx0, __shfl_xor_sync(0xffffffffu, mx0, 2));
        mx1 = fmaxf(mx1, __shfl_xor_sync(0xffffffffu, mx1, 1));
        mx1 = fmaxf(mx1, __shfl_xor_sync(0xffffffffu, mx1, 2));
        const float nm0 = fmaxf(m0, mx0), nm1 = fmaxf(m1, mx1);
        const float cf0 = ex2(m0 - nm0), cf1 = ex2(m1 - nm1);
        m0 = nm0; m1 = nm1;
        l0 *= cf0; l1 *= cf1;
#pragma unroll
        for (int nt = 0; nt < 8; nt++) {
            o[nt][0] *= cf0; o[nt][1] *= cf0;
            o[nt][2] *= cf1; o[nt][3] *= cf1;
        }
        // P = exp2(S - m); stage into Ps (permuted layout, tf32-rounded)
#pragma unroll
        for (int nt = 0; nt < 8; nt++) {
            const float p0 = ex2(s[nt][0] - m0), p1 = ex2(s[nt][1] - m0);
            const float p2 = ex2(s[nt][2] - m1), p3 = ex2(s[nt][3] - m1);
            l0 += p0 + p1;
            l1 += p2 + p3;
            const int c0 = nt * 8 + 2 * t;
            sts_col(Ps, KP, prow0, c0,     rnd_tf32(p0));
            sts_col(Ps, KP, prow0, c0 + 1, rnd_tf32(p1));
            sts_col(Ps, KP, prow1, c0,     rnd_tf32(p2));
            sts_col(Ps, KP, prow1, c0 + 1, rnd_tf32(p3));
        }
        if (more) ldgV(kt + 1);
        __syncwarp();

        // O += P @ V   (A-frags from Ps, B-frags from transposed V)
#pragma unroll
        for (int kp = 0; kp < 4; kp++) {
            const float4 alo = ldf(Ps, KP, prow0, kp, t);
            const float4 ahi = ldf(Ps, KP, prow1, kp, t);
#pragma unroll
            for (int nt = 0; nt < 8; nt++) {
                const float4 bv = ldf(Vb[cur], KP, nt * 8 + g, kp, t);
                mma_tf32(o[nt], alo.x, ahi.x, alo.y, ahi.y, bv.x, bv.y);
                mma_tf32(o[nt], alo.z, ahi.z, alo.w, ahi.w, bv.z, bv.w);
            }
        }
        if (more) stsV(nxt);
        __syncthreads();
    }

    l0 += __shfl_xor_sync(0xffffffffu, l0, 1);
    l0 += __shfl_xor_sync(0xffffffffu, l0, 2);
    l1 += __shfl_xor_sync(0xffffffffu, l1, 1);
    l1 += __shfl_xor_sync(0xffffffffu, l1, 2);
    const float inv0 = 1.f / l0, inv1 = 1.f / l1;

    float* ob = O + (size_t)(b * NN + q0 + w * 16) * DD + h * HD;
#pragma unroll
    for (int nt = 0; nt < 8; nt++) {
        const int col = nt * 8 + 2 * t;
        const float v0 = rnd_tf32(o[nt][0] * inv0);
        const float v1 = rnd_tf32(o[nt][1] * inv0);
        const float v2 = rnd_tf32(o[nt][2] * inv1);
        const float v3 = rnd_tf32(o[nt][3] * inv1);
        *(float2*)(ob + (size_t)g * DD + col) = make_float2(v0, v1);
        *(float2*)(ob + (size_t)(g + 8) * DD + col) = make_float2(v2, v3);
    }
}

// ---------------------------------------------------------------------------
// Launch
// ---------------------------------------------------------------------------
extern "C" void kernel_launch(void* const* d_in, const int* in_sizes, int n_in,
                              void* d_out, int out_size)
{
    const float* x  = (const float*)d_in[0];
    const float* Wq = (const float*)d_in[1];
    const float* Wk = (const float*)d_in[2];
    const float* Wv = (const float*)d_in[3];
    const float* Wo = (const float*)d_in[4];
    float* out = (float*)d_out;

    float *qkv, *o, *wqkv, *wot;
    cudaGetSymbolAddress((void**)&qkv,  g_qkv);
    cudaGetSymbolAddress((void**)&o,    g_o);
    cudaGetSymbolAddress((void**)&wqkv, g_wqkv);
    cudaGetSymbolAddress((void**)&wot,  g_wot);

    cudaFuncSetAttribute(attn_perm, cudaFuncAttributeMaxDynamicSharedMemorySize,
                         ATT_SMEM);
    cudaFuncSetAttribute(gemm_perm<true, false, true>,
                         cudaFuncAttributeMaxDynamicSharedMemorySize, GEMM_SMEM);
    cudaFuncSetAttribute(gemm_perm<false, false, false>,
                         cudaFuncAttributeMaxDynamicSharedMemorySize, GEMM_SMEM);

    // transpose + tf32-round weights
    transpose_round<<<dim3(DD / 32, DD / 32), dim3(32, 8)>>>(Wq, DD, DD, wqkv);
    transpose_round<<<dim3(KVD / 32, DD / 32), dim3(32, 8)>>>(Wk, DD, KVD,
        wqkv + (size_t)DD * DD);
    transpose_round<<<dim3(KVD / 32, DD / 32), dim3(32, 8)>>>(Wv, DD, KVD,
        wqkv + (size_t)(DD + KVD) * DD);
    transpose_round<<<dim3(DD / 32, DD / 32), dim3(32, 8)>>>(Wo, DD, DD, wot);

    // fused QKV projection: x rounded on smem store, output rounded
    gemm_perm<true, false, true>
        <<<dim3(QKVD / 128, MROWS / 128), 256, GEMM_SMEM>>>(
            MROWS, QKVD, DD, x, wqkv, qkv);

    // attention
    attn_perm<<<dim3(NN / 64, HH, BB), 128, ATT_SMEM>>>(qkv, o);

    // output projection (inputs pre-rounded), unrounded result
    gemm_perm<false, false, false>
        <<<dim3(DD / 128, MROWS / 128), 256, GEMM_SMEM>>>(
            MROWS, DD, DD, o, wot, out);
}

// round 8
// speedup vs baseline: 1.3556x; 1.3556x over previous
#include <cuda_runtime.h>
#include <cuda_bf16.h>
#include <cstdint>

// Problem constants
#define BB 2
#define NN 2048
#define DD 1024
#define HH 16
#define HKV 4
#define HD 64
#define REP 4
#define MROWS (BB * NN)      // 4096
#define KVD (HKV * HD)       // 256
#define QKVD (DD + 2 * KVD)  // 1536

// ---------------------------------------------------------------------------
// Scratch (static device globals)
// ---------------------------------------------------------------------------
__device__ float g_qkv[MROWS * QKVD];   // packed QKV projections (logical cols)
__device__ float g_o[MROWS * DD];       // attention out (hd cols PERMUTED, rounded)
__device__ float g_xp[MROWS * DD];      // x, k-cols permuted + rounded
__device__ float g_wqkv[QKVD * DD];     // Wq|Wk|Wv transposed [n][k], k permuted
__device__ float g_wot[DD * DD];        // Wo transposed [n][k], k permuted

// k-permutation within each 16-group: logical col c -> physical (c&3)*4+(c>>2)
#define PCOL(c) (((c) & ~15) | (((c) & 3) * 4 + (((c) & 15) >> 2)))

// ---------------------------------------------------------------------------
// Helpers
// ---------------------------------------------------------------------------
__device__ __forceinline__ uint32_t f2tf32(float x) {
    uint32_t r;
    asm("cvt.rna.tf32.f32 %0, %1;" : "=r"(r) : "f"(x));
    return r;
}
__device__ __forceinline__ float rnd_tf32(float x) {
    return __uint_as_float(f2tf32(x));
}
__device__ __forceinline__ float ex2(float x) {
    float r;
    asm("ex2.approx.ftz.f32 %0, %1;" : "=f"(r) : "f"(x));
    return r;
}
__device__ __forceinline__ void mma_tf32f(float* c, float a0, float a1,
                                          float a2, float a3,
                                          float b0, float b1) {
    asm volatile(
        "mma.sync.aligned.m16n8k8.row.col.f32.tf32.tf32.f32 "
        "{%0,%1,%2,%3}, {%4,%5,%6,%7}, {%8,%9}, {%0,%1,%2,%3};\n"
        : "+f"(c[0]), "+f"(c[1]), "+f"(c[2]), "+f"(c[3])
        : "r"(__float_as_uint(a0)), "r"(__float_as_uint(a1)),
          "r"(__float_as_uint(a2)), "r"(__float_as_uint(a3)),
          "r"(__float_as_uint(b0)), "r"(__float_as_uint(b1)));
}
__device__ __forceinline__ void mma_tf32(float* c, const uint32_t* a,
                                         uint32_t b0, uint32_t b1) {
    asm volatile(
        "mma.sync.aligned.m16n8k8.row.col.f32.tf32.tf32.f32 "
        "{%0,%1,%2,%3}, {%4,%5,%6,%7}, {%8,%9}, {%0,%1,%2,%3};\n"
        : "+f"(c[0]), "+f"(c[1]), "+f"(c[2]), "+f"(c[3])
        : "r"(a[0]), "r"(a[1]), "r"(a[2]), "r"(a[3]), "r"(b0), "r"(b1));
}
__device__ __forceinline__ void cp16(uint32_t dst, const void* src) {
    asm volatile("cp.async.ca.shared.global [%0], [%1], 16;"
                 :: "r"(dst), "l"(src));
}
#define CP_COMMIT() asm volatile("cp.async.commit_group;")
#define CP_WAIT(n)  asm volatile("cp.async.wait_group %0;" :: "n"(n))
__device__ __forceinline__ uint32_t smem_u32(const void* p) {
    return (uint32_t)__cvta_generic_to_shared(p);
}

// row-dependent quad XOR swizzle
__device__ __forceinline__ int swzf(int r) { return (r ^ (r >> 2)) & 3; }
// fragment read: 16B = logical cols {t,t+4,t+8,t+12} of group grp, row r
__device__ __forceinline__ float4 ldf(const float* base, int pitch, int r,
                                      int grp, int t) {
    return *(const float4*)(base + r * pitch + grp * 16 +
                            ((t ^ swzf(r)) << 2));
}

// ---------------------------------------------------------------------------
// Prep kernels
// ---------------------------------------------------------------------------
// Transpose + round + permute k: dst[c][perm(r)] = rnd(src[r][c])
__global__ void transpose_round_perm(const float* __restrict__ src, int R,
                                     int C, float* __restrict__ dst) {
    __shared__ float t[32][33];
    const int r0 = blockIdx.y * 32, c0 = blockIdx.x * 32;
    const int tx = threadIdx.x, ty = threadIdx.y;
#pragma unroll
    for (int i = 0; i < 32; i += 8)
        t[ty + i][tx] = src[(size_t)(r0 + ty + i) * C + c0 + tx];
    __syncthreads();
    const int ptx = (tx & 16) | ((tx & 3) * 4 + ((tx & 15) >> 2));
#pragma unroll
    for (int i = 0; i < 32; i += 8)
        dst[(size_t)(c0 + ty + i) * R + r0 + ptx] = rnd_tf32(t[tx][ty + i]);
}

// Permute k-cols within 16-groups + round: out[row][PCOL(c)] = rnd(in[row][c])
__global__ void permute_round(const float* __restrict__ in,
                              float* __restrict__ out, int n4) {
    int i = blockIdx.x * blockDim.x + threadIdx.x;
    if (i >= n4) return;
    const int row = i / (DD / 4);
    const int c0  = (i % (DD / 4)) * 4;
    float4 v = *(const float4*)(in + (size_t)row * DD + c0);
    float* ob = out + (size_t)row * DD;
    ob[PCOL(c0 + 0)] = rnd_tf32(v.x);
    ob[PCOL(c0 + 1)] = rnd_tf32(v.y);
    ob[PCOL(c0 + 2)] = rnd_tf32(v.z);
    ob[PCOL(c0 + 3)] = rnd_tf32(v.w);
}

// ---------------------------------------------------------------------------
// cp.async-fed tf32 GEMM. C[M,N] = A[M,K] @ Bt[N,K]^T, where A and Bt have
// k-columns pre-permuted by PCOL. 128x128 CTA tile, 32-k stages, 4-stage ring.
// Fragments read with conflict-free LDS.128 (quad-XOR swizzled layout).
// ---------------------------------------------------------------------------
#define GP 48                         // smem pitch (floats), 48%32=16 -> CF
#define STG_F (128 * GP)              // floats per operand per stage (6144)
#define GEMM_SMEM (4 * 2 * STG_F * 4) // 196608 bytes

template <bool RC>
__global__ __launch_bounds__(256) void gemm_cp(
    int M, int N, int K,
    const float* __restrict__ A, const float* __restrict__ Bt,
    float* __restrict__ C)
{
    extern __shared__ float sm[];

    const int tid  = threadIdx.x;
    const int lane = tid & 31;
    const int w    = tid >> 5;
    const int g    = lane >> 2;
    const int t    = lane & 3;
    const int wm   = (w & 3) * 32;
    const int wn   = (w >> 2) * 64;
    const int bm   = blockIdx.y * 128;
    const int bn   = blockIdx.x * 128;
    const int NS   = K / 32;

    // cp.async mapping: thread covers row tid>>1, 16B chunks (tid&1)*4 + 0..3
    const int lrow = tid >> 1;
    const int jb   = (tid & 1) * 4;
    const uint32_t smb = smem_u32(sm);

    auto issue = [&](int s) {
        const int st = s & 3;
        const uint32_t ab = smb + (st * 2) * STG_F * 4;
        const uint32_t bb = ab + STG_F * 4;
        const float* Ag = A + (size_t)(bm + lrow) * K + s * 32;
        const float* Bg = Bt + (size_t)(bn + lrow) * K + s * 32;
        const int sz = swzf(lrow);
        const uint32_t rowoff = lrow * GP * 4;
#pragma unroll
        for (int i = 0; i < 4; i++) {
            const int j   = jb + i;              // 16B chunk 0..7
            const int grp = j >> 2, jj = j & 3;
            const uint32_t doff = rowoff + grp * 64 + ((jj ^ sz) << 4);
            cp16(ab + doff, Ag + j * 4);
            cp16(bb + doff, Bg + j * 4);
        }
        CP_COMMIT();
    };

    float acc[2][8][4];
#pragma unroll
    for (int mt = 0; mt < 2; mt++)
#pragma unroll
        for (int nt = 0; nt < 8; nt++)
#pragma unroll
            for (int j = 0; j < 4; j++) acc[mt][nt][j] = 0.f;

    issue(0); issue(1); issue(2);

    for (int s = 0; s < NS; s++) {
        const int st = s & 3;
        const int pend = NS - 1 - s;
        if (pend >= 2)      CP_WAIT(2);
        else if (pend == 1) CP_WAIT(1);
        else                CP_WAIT(0);
        __syncthreads();

        if (s + 3 < NS) issue(s + 3);   // buffer (s-1)&3 freed by the sync

        const float* Ac = sm + (st * 2) * STG_F;
        const float* Bc = Ac + STG_F;
#pragma unroll
        for (int kp = 0; kp < 2; kp++) {
            float4 alo[2], ahi[2];
#pragma unroll
            for (int mt = 0; mt < 2; mt++) {
                const int rlo = wm + mt * 16 + g;
                alo[mt] = ldf(Ac, GP, rlo, kp, t);
                ahi[mt] = ldf(Ac, GP, rlo + 8, kp, t);
            }
#pragma unroll
            for (int nt = 0; nt < 8; nt++) {
                const float4 bv = ldf(Bc, GP, wn + nt * 8 + g, kp, t);
#pragma unroll
                for (int mt = 0; mt < 2; mt++) {
                    mma_tf32f(acc[mt][nt], alo[mt].x, ahi[mt].x, alo[mt].y,
                              ahi[mt].y, bv.x, bv.y);
                    mma_tf32f(acc[mt][nt], alo[mt].z, ahi[mt].z, alo[mt].w,
                              ahi[mt].w, bv.z, bv.w);
                }
            }
        }
        __syncthreads();   // all warps done with stage st before refill
    }

#pragma unroll
    for (int mt = 0; mt < 2; mt++)
#pragma unroll
        for (int nt = 0; nt < 8; nt++) {
            const int row = bm + wm + mt * 16 + g;
            const int col = bn + wn + nt * 8 + 2 * t;
            float v0 = acc[mt][nt][0], v1 = acc[mt][nt][1];
            float v2 = acc[mt][nt][2], v3 = acc[mt][nt][3];
            if (RC) {
                v0 = rnd_tf32(v0); v1 = rnd_tf32(v1);
                v2 = rnd_tf32(v2); v3 = rnd_tf32(v3);
            }
            *(float2*)(C + (size_t)row * N + col) = make_float2(v0, v1);
            *(float2*)(C + (size_t)(row + 8) * N + col) = make_float2(v2, v3);
        }
}

// ---------------------------------------------------------------------------
// Tensor-core flash attention (tf32 mma.sync), cp.async double-buffered K/V.
// EXACT Round-4 kernel; only the epilogue stores o with PCOL-permuted hd cols
// (pre-permuting the A-operand of the Wo GEMM).
// ---------------------------------------------------------------------------
#define KS_STRIDE 68
#define VS_STRIDE 72
#define PS_STRIDE 72
#define NT (NN / 64)
#define ATT_SMEM ((2 * 64 * KS_STRIDE + 2 * 64 * VS_STRIDE + 64 * PS_STRIDE) * 4)

__global__ __launch_bounds__(128, 2) void attn_tc(
    const float* __restrict__ QKV, float* __restrict__ O)
{
    extern __shared__ float smf[];
    float* KsS[2] = { smf, smf + 64 * KS_STRIDE };
    float* VsS[2] = { smf + 2 * 64 * KS_STRIDE,
                      smf + 2 * 64 * KS_STRIDE + 64 * VS_STRIDE };
    float* Ps = smf + 2 * 64 * KS_STRIDE + 2 * 64 * VS_STRIDE;

    const int tid  = threadIdx.x;
    const int lane = tid & 31;
    const int w    = tid >> 5;
    const int g    = lane >> 2;
    const int t    = lane & 3;
    const int b    = blockIdx.z;
    const int h    = blockIdx.y;
    const int q0   = blockIdx.x * 64;
    const int kvh  = h >> 2;
    const float SCALE = 0.125f * 1.4426950408889634f;

    const float* kbase = QKV + (size_t)b * NN * QKVD + DD + kvh * HD;
    const float* vbase = QKV + (size_t)b * NN * QKVD + DD + KVD + kvh * HD;

    const int lr  = tid >> 4;
    const int lc4 = (tid & 15) * 4;

    auto issue_tile = [&](int stage, int kt) {
        uint32_t kdst = smem_u32(KsS[stage] + lr * KS_STRIDE + lc4);
        uint32_t vdst = smem_u32(VsS[stage] + lr * VS_STRIDE + lc4);
        const float* ksrc = kbase + (size_t)(kt * 64 + lr) * QKVD + lc4;
        const float* vsrc = vbase + (size_t)(kt * 64 + lr) * QKVD + lc4;
#pragma unroll
        for (int i = 0; i < 8; i++) {
            cp16(kdst + i * 8 * KS_STRIDE * 4, ksrc + (size_t)8 * i * QKVD);
            cp16(vdst + i * 8 * VS_STRIDE * 4, vsrc + (size_t)8 * i * QKVD);
        }
    };

    uint32_t qa[8][4];
    {
        const float* qb = QKV + (size_t)(b * NN + q0 + w * 16) * QKVD + h * HD;
#pragma unroll
        for (int kf = 0; kf < 8; kf++) {
            qa[kf][0] = f2tf32(qb[(size_t)g * QKVD + kf * 8 + t] * SCALE);
            qa[kf][1] = f2tf32(qb[(size_t)(g + 8) * QKVD + kf * 8 + t] * SCALE);
            qa[kf][2] = f2tf32(qb[(size_t)g * QKVD + kf * 8 + t + 4] * SCALE);
            qa[kf][3] = f2tf32(qb[(size_t)(g + 8) * QKVD + kf * 8 + t + 4] * SCALE);
        }
    }

    float o[8][4];
#pragma unroll
    for (int nt = 0; nt < 8; nt++)
#pragma unroll
        for (int j = 0; j < 4; j++) o[nt][j] = 0.f;
    float m0 = -1e30f, m1 = -1e30f, l0 = 0.f, l1 = 0.f;

    issue_tile(0, 0);
    CP_COMMIT();

    for (int kt = 0; kt < NT; kt++) {
        const int st = kt & 1;
        if (kt + 1 < NT) {
            issue_tile(st ^ 1, kt + 1);
            CP_COMMIT();
            CP_WAIT(1);
        } else {
            CP_WAIT(0);
        }
        __syncthreads();

        const float* Ks = KsS[st];
        const float* Vs = VsS[st];

        float s[8][4];
#pragma unroll
        for (int nt = 0; nt < 8; nt++)
#pragma unroll
            for (int j = 0; j < 4; j++) s[nt][j] = 0.f;
#pragma unroll
        for (int kf = 0; kf < 8; kf++) {
#pragma unroll
            for (int nt = 0; nt < 8; nt++) {
                const float* kr = &Ks[(nt * 8 + g) * KS_STRIDE + kf * 8 + t];
                uint32_t b0 = __float_as_uint(kr[0]);
                uint32_t b1 = __float_as_uint(kr[4]);
                mma_tf32(s[nt], qa[kf], b0, b1);
            }
        }

        float mx0 = -1e30f, mx1 = -1e30f;
#pragma unroll
        for (int nt = 0; nt < 8; nt++) {
            mx0 = fmaxf(mx0, fmaxf(s[nt][0], s[nt][1]));
            mx1 = fmaxf(mx1, fmaxf(s[nt][2], s[nt][3]));
        }
        mx0 = fmaxf(mx0, __shfl_xor_sync(0xffffffffu, mx0, 1));
        mx0 = fmaxf(mx0, __shfl_xor_sync(0xffffffffu, mx0, 2));
        mx1 = fmaxf(mx1, __shfl_xor_sync(0xffffffffu, mx1, 1));
        mx1 = fmaxf(mx1, __shfl_xor_sync(0xffffffffu, mx1, 2));
        const float nm0 = fmaxf(m0, mx0), nm1 = fmaxf(m1, mx1);
        const float cf0 = ex2(m0 - nm0), cf1 = ex2(m1 - nm1);
        m0 = nm0; m1 = nm1;
        l0 *= cf0; l1 *= cf1;
#pragma unroll
        for (int nt = 0; nt < 8; nt++) {
            o[nt][0] *= cf0; o[nt][1] *= cf0;
            o[nt][2] *= cf1; o[nt][3] *= cf1;
        }
#pragma unroll
        for (int nt = 0; nt < 8; nt++) {
            float p0 = ex2(s[nt][0] - m0), p1 = ex2(s[nt][1] - m0);
            float p2 = ex2(s[nt][2] - m1), p3 = ex2(s[nt][3] - m1);
            l0 += p0 + p1;
            l1 += p2 + p3;
            uint2 u01 = make_uint2(f2tf32(p0), f2tf32(p1));
            uint2 u23 = make_uint2(f2tf32(p2), f2tf32(p3));
            *(uint2*)&Ps[(w * 16 + g) * PS_STRIDE + nt * 8 + 2 * t] = u01;
            *(uint2*)&Ps[(w * 16 + g + 8) * PS_STRIDE + nt * 8 + 2 * t] = u23;
        }
        __syncwarp();

#pragma unroll
        for (int kf = 0; kf < 8; kf++) {
            uint32_t a[4];
            a[0] = __float_as_uint(Ps[(w * 16 + g) * PS_STRIDE + kf * 8 + t]);
            a[1] = __float_as_uint(Ps[(w * 16 + g + 8) * PS_STRIDE + kf * 8 + t]);
            a[2] = __float_as_uint(Ps[(w * 16 + g) * PS_STRIDE + kf * 8 + t + 4]);
            a[3] = __float_as_uint(Ps[(w * 16 + g + 8) * PS_STRIDE + kf * 8 + t + 4]);
#pragma unroll
            for (int nt = 0; nt < 8; nt++) {
                uint32_t b0 = __float_as_uint(Vs[(kf * 8 + t) * VS_STRIDE + nt * 8 + g]);
                uint32_t b1 = __float_as_uint(Vs[(kf * 8 + t + 4) * VS_STRIDE + nt * 8 + g]);
                mma_tf32(o[nt], a, b0, b1);
            }
        }
        __syncthreads();
    }

    l0 += __shfl_xor_sync(0xffffffffu, l0, 1);
    l0 += __shfl_xor_sync(0xffffffffu, l0, 2);
    l1 += __shfl_xor_sync(0xffffffffu, l1, 1);
    l1 += __shfl_xor_sync(0xffffffffu, l1, 2);
    const float inv0 = 1.f / l0, inv1 = 1.f / l1;

    // epilogue: store with PCOL-permuted hd columns (A-operand of Wo GEMM)
    float* ob = O + (size_t)(b * NN + q0 + w * 16) * DD + h * HD;
#pragma unroll
    for (int nt = 0; nt < 8; nt++) {
        const int c0 = nt * 8 + 2 * t;
        ob[(size_t)g * DD + PCOL(c0)]           = rnd_tf32(o[nt][0] * inv0);
        ob[(size_t)g * DD + PCOL(c0 + 1)]       = rnd_tf32(o[nt][1] * inv0);
        ob[(size_t)(g + 8) * DD + PCOL(c0)]     = rnd_tf32(o[nt][2] * inv1);
        ob[(size_t)(g + 8) * DD + PCOL(c0 + 1)] = rnd_tf32(o[nt][3] * inv1);
    }
}

// ---------------------------------------------------------------------------
// Launch
// ---------------------------------------------------------------------------
extern "C" void kernel_launch(void* const* d_in, const int* in_sizes, int n_in,
                              void* d_out, int out_size)
{
    const float* x  = (const float*)d_in[0];
    const float* Wq = (const float*)d_in[1];
    const float* Wk = (const float*)d_in[2];
    const float* Wv = (const float*)d_in[3];
    const float* Wo = (const float*)d_in[4];
    float* out = (float*)d_out;

    float *qkv, *o, *xp, *wqkv, *wot;
    cudaGetSymbolAddress((void**)&qkv,  g_qkv);
    cudaGetSymbolAddress((void**)&o,    g_o);
    cudaGetSymbolAddress((void**)&xp,   g_xp);
    cudaGetSymbolAddress((void**)&wqkv, g_wqkv);
    cudaGetSymbolAddress((void**)&wot,  g_wot);

    cudaFuncSetAttribute(attn_tc, cudaFuncAttributeMaxDynamicSharedMemorySize,
                         ATT_SMEM);
    cudaFuncSetAttribute(gemm_cp<true>,
                         cudaFuncAttributeMaxDynamicSharedMemorySize, GEMM_SMEM);
    cudaFuncSetAttribute(gemm_cp<false>,
                         cudaFuncAttributeMaxDynamicSharedMemorySize, GEMM_SMEM);

    // weights: transpose + round + permute k
    transpose_round_perm<<<dim3(DD / 32, DD / 32), dim3(32, 8)>>>(Wq, DD, DD, wqkv);
    transpose_round_perm<<<dim3(KVD / 32, DD / 32), dim3(32, 8)>>>(Wk, DD, KVD,
        wqkv + (size_t)DD * DD);
    transpose_round_perm<<<dim3(KVD / 32, DD / 32), dim3(32, 8)>>>(Wv, DD, KVD,
        wqkv + (size_t)(DD + KVD) * DD);
    transpose_round_perm<<<dim3(DD / 32, DD / 32), dim3(32, 8)>>>(Wo, DD, DD, wot);

    // x: permute k-cols + round
    {
        const int n4 = MROWS * DD / 4;
        permute_round<<<(n4 + 255) / 256, 256>>>(x, xp, n4);
    }

    // fused QKV projection (cp.async GEMM), output rounded, logical layout
    gemm_cp<true><<<dim3(QKVD / 128, MROWS / 128), 256, GEMM_SMEM>>>(
        MROWS, QKVD, DD, xp, wqkv, qkv);

    // attention (R4-proven); writes o permuted + rounded
    attn_tc<<<dim3(NN / 64, HH, BB), 128, ATT_SMEM>>>(qkv, o);

    // output projection
    gemm_cp<false><<<dim3(DD / 128, MROWS / 128), 256, GEMM_SMEM>>>(
        MROWS, DD, DD, o, wot, out);
}

// round 10
// speedup vs baseline: 3.1217x; 2.3029x over previous
#include <cuda_runtime.h>
#include <cuda_fp16.h>
#include <cuda_bf16.h>
#include <cstdint>

// Problem constants
#define BB 2
#define NN 2048
#define DD 1024
#define HH 16
#define HKV 4
#define HD 64
#define REP 4
#define MROWS (BB * NN)      // 4096
#define KVD (HKV * HD)       // 256
#define QKVD (DD + 2 * KVD)  // 1536
#define NT (NN / 64)         // 32 kv tiles

// ---------------------------------------------------------------------------
// Scratch (static device globals)
// ---------------------------------------------------------------------------
__device__ __half g_qkv[MROWS * QKVD];   // packed QKV projections (fp16)
__device__ __half g_o[MROWS * DD];       // attention out (fp16)
__device__ __half g_xh[MROWS * DD];      // x in fp16
__device__ __half g_wqkv[QKVD * DD];     // Wq|Wk|Wv transposed [n][k] fp16
__device__ __half g_wot[DD * DD];        // Wo transposed [n][k] fp16
__device__ __half g_vt[BB * KVD * NN];   // V transposed: [b][kvh*64+hd][n]

// ---------------------------------------------------------------------------
// Helpers
// ---------------------------------------------------------------------------
__device__ __forceinline__ float ex2(float x) {
    float r;
    asm("ex2.approx.ftz.f32 %0, %1;" : "=f"(r) : "f"(x));
    return r;
}
// D(16x8) += A(16x16) * B(16x8), fp16 in, fp32 acc
__device__ __forceinline__ void mma_h(float* c, const uint32_t* a,
                                      uint32_t b0, uint32_t b1) {
    asm volatile(
        "mma.sync.aligned.m16n8k16.row.col.f32.f16.f16.f32 "
        "{%0,%1,%2,%3}, {%4,%5,%6,%7}, {%8,%9}, {%0,%1,%2,%3};\n"
        : "+f"(c[0]), "+f"(c[1]), "+f"(c[2]), "+f"(c[3])
        : "r"(a[0]), "r"(a[1]), "r"(a[2]), "r"(a[3]), "r"(b0), "r"(b1));
}
__device__ __forceinline__ void ldm4(uint32_t& r0, uint32_t& r1, uint32_t& r2,
                                     uint32_t& r3, uint32_t addr) {
    asm volatile(
        "ldmatrix.sync.aligned.m8n8.x4.shared.b16 {%0,%1,%2,%3}, [%4];"
        : "=r"(r0), "=r"(r1), "=r"(r2), "=r"(r3) : "r"(addr));
}
__device__ __forceinline__ void cp16(uint32_t dst, const void* src) {
    asm volatile("cp.async.ca.shared.global [%0], [%1], 16;"
                 :: "r"(dst), "l"(src));
}
#define CP_COMMIT() asm volatile("cp.async.commit_group;")
#define CP_WAIT(n)  asm volatile("cp.async.wait_group %0;" :: "n"(n))
__device__ __forceinline__ uint32_t smem_u32(const void* p) {
    return (uint32_t)__cvta_generic_to_shared(p);
}

// ---------------------------------------------------------------------------
// Prep kernels
// ---------------------------------------------------------------------------
// fp32 -> fp16 flat convert
__global__ void conv_half(const float* __restrict__ in,
                          __half* __restrict__ out, int n4) {
    int i = blockIdx.x * blockDim.x + threadIdx.x;
    if (i >= n4) return;
    float4 v = ((const float4*)in)[i];
    __half2* o2 = (__half2*)(out + (size_t)i * 4);
    o2[0] = __floats2half2_rn(v.x, v.y);
    o2[1] = __floats2half2_rn(v.z, v.w);
}

// transpose + scale + convert: src fp32 [1024][C] -> dst fp16 [C][1024]
__global__ void transpose_h(const float* __restrict__ src, int C, float scale,
                            __half* __restrict__ dst) {
    __shared__ float t[32][33];
    const int r0 = blockIdx.y * 32, c0 = blockIdx.x * 32;
    const int tx = threadIdx.x, ty = threadIdx.y;
#pragma unroll
    for (int i = 0; i < 32; i += 8)
        t[ty + i][tx] = src[(size_t)(r0 + ty + i) * C + c0 + tx];
    __syncthreads();
#pragma unroll
    for (int i = 0; i < 32; i += 8)
        dst[(size_t)(c0 + ty + i) * DD + r0 + tx] =
            __float2half(t[tx][ty + i] * scale);
}

// V region of qkv -> vt[b*KVD + c][n]  (fp16 transpose)
__global__ void vtrans(const __half* __restrict__ qkv,
                       __half* __restrict__ vt) {
    __shared__ __half t[32][33];
    const int b  = blockIdx.z;
    const int n0 = blockIdx.x * 32, c0 = blockIdx.y * 32;
    const int tx = threadIdx.x, ty = threadIdx.y;
#pragma unroll
    for (int i = 0; i < 32; i += 8)
        t[ty + i][tx] = qkv[(size_t)(b * NN + n0 + ty + i) * QKVD +
                            DD + KVD + c0 + tx];
    __syncthreads();
#pragma unroll
    for (int i = 0; i < 32; i += 8)
        vt[(size_t)(b * KVD + c0 + ty + i) * NN + n0 + tx] = t[tx][ty + i];
}

// ---------------------------------------------------------------------------
// fp16 GEMM: C[M,N] = A[M,1024] @ Bt[N,1024]^T. 128x128 CTA tile, 8 warps,
// warp tile 32x64, m16n8k16, ldmatrix feeds, 4-stage cp.async ring (k=32/stage)
// ---------------------------------------------------------------------------
#define PH 40                  // stage pitch in halves (32 data + 8 pad)
#define STGH (128 * PH)        // halves per operand per stage
#define GSMEM (4 * 2 * STGH * 2)  // 81920 bytes

template <bool HOUT>
__global__ __launch_bounds__(256, 2) void gemm_h(
    int M, int N, const __half* __restrict__ A, const __half* __restrict__ Bt,
    void* __restrict__ Cvoid)
{
    extern __shared__ __half hsm[];
    const uint32_t smb = smem_u32(hsm);

    const int tid  = threadIdx.x;
    const int lane = tid & 31;
    const int w    = tid >> 5;
    const int g    = lane >> 2;
    const int t    = lane & 3;
    const int wm   = (w & 3) * 32;
    const int wn   = (w >> 2) * 64;
    const int bm   = blockIdx.y * 128;
    const int bn   = blockIdx.x * 128;
    const int NS   = 1024 / 32;

    // ldmatrix per-lane address components
    const int arow = (lane & 15);                          // A/P pattern
    const int ach  = (lane >> 4);                          // chunk parity
    const int brow = (lane & 7) + ((lane >> 4) << 3);      // B pattern
    const int bch  = (lane >> 3) & 1;

    auto issue = [&](int s) {
        const int st = s & 3;
        const uint32_t ua = smb + st * 2 * STGH * 2;
        const uint32_t ub = ua + STGH * 2;
#pragma unroll
        for (int i = 0; i < 2; i++) {
            const int c   = tid + i * 256;   // 512 chunks (rows x 4 chunks)
            const int row = c >> 2, ch = c & 3;
            cp16(ua + (row * PH + ch * 8) * 2,
                 A + (size_t)(bm + row) * 1024 + s * 32 + ch * 8);
            cp16(ub + (row * PH + ch * 8) * 2,
                 Bt + (size_t)(bn + row) * 1024 + s * 32 + ch * 8);
        }
        CP_COMMIT();
    };

    float acc[2][8][4];
#pragma unroll
    for (int mt = 0; mt < 2; mt++)
#pragma unroll
        for (int nt = 0; nt < 8; nt++)
#pragma unroll
            for (int j = 0; j < 4; j++) acc[mt][nt][j] = 0.f;

    issue(0); issue(1); issue(2);

    for (int s = 0; s < NS; s++) {
        const int st = s & 3;
        const int pend = NS - 1 - s;
        if (pend >= 2)      CP_WAIT(2);
        else if (pend == 1) CP_WAIT(1);
        else                CP_WAIT(0);
        __syncthreads();
        if (s + 3 < NS) issue(s + 3);

        const uint32_t uA = smb + st * 2 * STGH * 2;
        const uint32_t uB = uA + STGH * 2;
#pragma unroll
        for (int kf = 0; kf < 2; kf++) {
            uint32_t a[2][4];
#pragma unroll
            for (int mt = 0; mt < 2; mt++)
                ldm4(a[mt][0], a[mt][1], a[mt][2], a[mt][3],
                     uA + ((wm + mt * 16 + arow) * PH +
                           (2 * kf + ach) * 8) * 2);
#pragma unroll
            for (int nt2 = 0; nt2 < 4; nt2++) {
                uint32_t b0, b1, b2, b3;
                ldm4(b0, b1, b2, b3,
                     uB + ((wn + nt2 * 16 + brow) * PH +
                           (2 * kf + bch) * 8) * 2);
#pragma unroll
                for (int mt = 0; mt < 2; mt++) {
                    mma_h(acc[mt][2 * nt2],     a[mt], b0, b1);
                    mma_h(acc[mt][2 * nt2 + 1], a[mt], b2, b3);
                }
            }
        }
        __syncthreads();
    }

#pragma unroll
    for (int mt = 0; mt < 2; mt++)
#pragma unroll
        for (int nt = 0; nt < 8; nt++) {
            const int row = bm + wm + mt * 16 + g;
            const int col = bn + wn + nt * 8 + 2 * t;
            if (HOUT) {
                __half* C = (__half*)Cvoid;
                *(__half2*)(C + (size_t)row * N + col) =
                    __floats2half2_rn(acc[mt][nt][0], acc[mt][nt][1]);
                *(__half2*)(C + (size_t)(row + 8) * N + col) =
                    __floats2half2_rn(acc[mt][nt][2], acc[mt][nt][3]);
            } else {
                float* C = (float*)Cvoid;
                *(float2*)(C + (size_t)row * N + col) =
                    make_float2(acc[mt][nt][0], acc[mt][nt][1]);
                *(float2*)(C + (size_t)(row + 8) * N + col) =
                    make_float2(acc[mt][nt][2], acc[mt][nt][3]);
            }
        }
}

// ---------------------------------------------------------------------------
// fp16 flash attention. Br=64 (4 warps x 16 rows), Bc=64, m16n8k16.
// K tile from qkv [kv][hd]; V tile from vt [hd][kv]; both ldmatrix-fed.
// Q pre-scaled by 1/sqrt(HD)*log2(e) (folded into Wq). fp32 softmax/acc.
// ---------------------------------------------------------------------------
#define AP 72                       // attention pitch (64 data + 8 pad halves)
#define ATILEH (64 * AP)
#define ASMEM (5 * ATILEH * 2)      // K0,K1,V0,V1,Ps = 46080 bytes

__global__ __launch_bounds__(128, 3) void attn_h(
    const __half* __restrict__ qkv, const __half* __restrict__ vt,
    __half* __restrict__ O)
{
    extern __shared__ __half hsm[];
    const uint32_t smb = smem_u32(hsm);
    const uint32_t uK[2] = { smb, smb + ATILEH * 2 };
    const uint32_t uV[2] = { smb + 2 * ATILEH * 2, smb + 3 * ATILEH * 2 };
    const uint32_t uP    = smb + 4 * ATILEH * 2;
    __half* Ps = hsm + 4 * ATILEH;

    const int tid  = threadIdx.x;
    const int lane = tid & 31;
    const int w    = tid >> 5;
    const int g    = lane >> 2;
    const int t    = lane & 3;
    const int b    = blockIdx.z;
    const int h    = blockIdx.y;
    const int q0   = blockIdx.x * 64;
    const int kvh  = h >> 2;

    const int arow = (lane & 15);
    const int ach  = (lane >> 4);
    const int brow = (lane & 7) + ((lane >> 4) << 3);
    const int bch  = (lane >> 3) & 1;

    // Tile rows are 64 halves wide = 8 x 16B chunks -> 64*8 = 512 chunks.
    // (Round-9 bug: covered only chunks 0..3 -> upper half of K/V tiles
    //  was uninitialized smem -> NaN. Now 4 iters x 128 thr, row=c>>3, ch=c&7.)
    auto issue_tile = [&](int stage, int kt) {
#pragma unroll
        for (int i = 0; i < 4; i++) {
            const int c   = tid + i * 128;
            const int row = c >> 3, ch = c & 7;
            cp16(uK[stage] + (row * AP + ch * 8) * 2,
                 qkv + (size_t)(b * NN + kt * 64 + row) * QKVD +
                     DD + kvh * HD + ch * 8);
            cp16(uV[stage] + (row * AP + ch * 8) * 2,
                 vt + (size_t)(b * KVD + kvh * HD + row) * NN +
                     kt * 64 + ch * 8);
        }
        CP_COMMIT();
    };

    // Q fragments (pre-scaled fp16, registers whole kernel)
    uint32_t qa[4][4];
    {
        const __half* qb = qkv + (size_t)(b * NN + q0 + w * 16) * QKVD + h * HD;
#pragma unroll
        for (int kf = 0; kf < 4; kf++) {
            qa[kf][0] = *(const uint32_t*)(qb + (size_t)g * QKVD + kf * 16 + 2 * t);
            qa[kf][1] = *(const uint32_t*)(qb + (size_t)(g + 8) * QKVD + kf * 16 + 2 * t);
            qa[kf][2] = *(const uint32_t*)(qb + (size_t)g * QKVD + kf * 16 + 8 + 2 * t);
            qa[kf][3] = *(const uint32_t*)(qb + (size_t)(g + 8) * QKVD + kf * 16 + 8 + 2 * t);
        }
    }

    float o[8][4];
#pragma unroll
    for (int nt = 0; nt < 8; nt++)
#pragma unroll
        for (int j = 0; j < 4; j++) o[nt][j] = 0.f;
    float m0 = -1e30f, m1 = -1e30f, l0 = 0.f, l1 = 0.f;

    issue_tile(0, 0);

    const int prow0 = w * 16 + g, prow1 = prow0 + 8;

    for (int kt = 0; kt < NT; kt++) {
        const int cur = kt & 1;
        if (kt + 1 < NT) {
            issue_tile(cur ^ 1, kt + 1);
            CP_WAIT(1);
        } else {
            CP_WAIT(0);
        }
        __syncthreads();

        // S = Q @ K^T  (16 x 64)
        float s[8][4];
#pragma unroll
        for (int nt = 0; nt < 8; nt++)
#pragma unroll
            for (int j = 0; j < 4; j++) s[nt][j] = 0.f;
#pragma unroll
        for (int kf = 0; kf < 4; kf++) {
#pragma unroll
            for (int nt2 = 0; nt2 < 4; nt2++) {
                uint32_t b0, b1, b2, b3;
                ldm4(b0, b1, b2, b3,
                     uK[cur] + ((nt2 * 16 + brow) * AP +
                                (2 * kf + bch) * 8) * 2);
                mma_h(s[2 * nt2],     qa[kf], b0, b1);
                mma_h(s[2 * nt2 + 1], qa[kf], b2, b3);
            }
        }

        // online softmax (rows g, g+8); S already in log2 domain
        float mx0 = -1e30f, mx1 = -1e30f;
#pragma unroll
        for (int nt = 0; nt < 8; nt++) {
            mx0 = fmaxf(mx0, fmaxf(s[nt][0], s[nt][1]));
            mx1 = fmaxf(mx1, fmaxf(s[nt][2], s[nt][3]));
        }
        mx0 = fmaxf(mx0, __shfl_xor_sync(0xffffffffu, mx0, 1));
        mx0 = fmaxf(mx0, __shfl_xor_sync(0xffffffffu, mx0, 2));
        mx1 = fmaxf(mx1, __shfl_xor_sync(0xffffffffu, mx1, 1));
        mx1 = fmaxf(mx1, __shfl_xor_sync(0xffffffffu, mx1, 2));
        const float nm0 = fmaxf(m0, mx0), nm1 = fmaxf(m1, mx1);
        const float cf0 = ex2(m0 - nm0), cf1 = ex2(m1 - nm1);
        m0 = nm0; m1 = nm1;
        l0 *= cf0; l1 *= cf1;
#pragma unroll
        for (int nt = 0; nt < 8; nt++) {
            o[nt][0] *= cf0; o[nt][1] *= cf0;
            o[nt][2] *= cf1; o[nt][3] *= cf1;
        }
        // P = exp2(S - m) -> fp16 -> Ps (half2 stores, conflict-free)
#pragma unroll
        for (int nt = 0; nt < 8; nt++) {
            const float p0 = ex2(s[nt][0] - m0), p1 = ex2(s[nt][1] - m0);
            const float p2 = ex2(s[nt][2] - m1), p3 = ex2(s[nt][3] - m1);
            l0 += p0 + p1;
            l1 += p2 + p3;
            *(__half2*)(Ps + prow0 * AP + nt * 8 + 2 * t) =
                __floats2half2_rn(p0, p1);
            *(__half2*)(Ps + prow1 * AP + nt * 8 + 2 * t) =
                __floats2half2_rn(p2, p3);
        }
        __syncwarp();

        // O += P @ V (A-frags: ldmatrix from Ps; B-frags: ldmatrix from Vt)
#pragma unroll
        for (int kf = 0; kf < 4; kf++) {
            uint32_t pa[4];
            ldm4(pa[0], pa[1], pa[2], pa[3],
                 uP + ((w * 16 + arow) * AP + (2 * kf + ach) * 8) * 2);
#pragma unroll
            for (int nt2 = 0; nt2 < 4; nt2++) {
                uint32_t b0, b1, b2, b3;
                ldm4(b0, b1, b2, b3,
                     uV[cur] + ((nt2 * 16 + brow) * AP +
                                (2 * kf + bch) * 8) * 2);
                mma_h(o[2 * nt2],     pa, b0, b1);
                mma_h(o[2 * nt2 + 1], pa, b2, b3);
            }
        }
        __syncthreads();
    }

    l0 += __shfl_xor_sync(0xffffffffu, l0, 1);
    l0 += __shfl_xor_sync(0xffffffffu, l0, 2);
    l1 += __shfl_xor_sync(0xffffffffu, l1, 1);
    l1 += __shfl_xor_sync(0xffffffffu, l1, 2);
    const float inv0 = 1.f / l0, inv1 = 1.f / l1;

    __half* ob = O + (size_t)(b * NN + q0 + w * 16) * DD + h * HD;
#pragma unroll
    for (int nt = 0; nt < 8; nt++) {
        const int col = nt * 8 + 2 * t;
        *(__half2*)(ob + (size_t)g * DD + col) =
            __floats2half2_rn(o[nt][0] * inv0, o[nt][1] * inv0);
        *(__half2*)(ob + (size_t)(g + 8) * DD + col) =
            __floats2half2_rn(o[nt][2] * inv1, o[nt][3] * inv1);
    }
}

// ---------------------------------------------------------------------------
// Launch
// ---------------------------------------------------------------------------
extern "C" void kernel_launch(void* const* d_in, const int* in_sizes, int n_in,
                              void* d_out, int out_size)
{
    const float* x  = (const float*)d_in[0];
    const float* Wq = (const float*)d_in[1];
    const float* Wk = (const float*)d_in[2];
    const float* Wv = (const float*)d_in[3];
    const float* Wo = (const float*)d_in[4];
    float* out = (float*)d_out;

    __half *qkv, *o, *xh, *wqkv, *wot, *vt;
    cudaGetSymbolAddress((void**)&qkv,  g_qkv);
    cudaGetSymbolAddress((void**)&o,    g_o);
    cudaGetSymbolAddress((void**)&xh,   g_xh);
    cudaGetSymbolAddress((void**)&wqkv, g_wqkv);
    cudaGetSymbolAddress((void**)&wot,  g_wot);
    cudaGetSymbolAddress((void**)&vt,   g_vt);

    cudaFuncSetAttribute(attn_h, cudaFuncAttributeMaxDynamicSharedMemorySize,
                         ASMEM);
    cudaFuncSetAttribute(gemm_h<true>,
                         cudaFuncAttributeMaxDynamicSharedMemorySize, GSMEM);
    cudaFuncSetAttribute(gemm_h<false>,
                         cudaFuncAttributeMaxDynamicSharedMemorySize, GSMEM);

    const float QSCALE = 0.125f * 1.4426950408889634f;  // 1/sqrt(64)*log2(e)

    // prep: x -> fp16; weights -> transposed fp16 (Wq pre-scaled)
    {
        const int n4 = MROWS * DD / 4;
        conv_half<<<(n4 + 255) / 256, 256>>>(x, xh, n4);
    }
    transpose_h<<<dim3(DD / 32, DD / 32), dim3(32, 8)>>>(Wq, DD, QSCALE, wqkv);
    transpose_h<<<dim3(KVD / 32, DD / 32), dim3(32, 8)>>>(Wk, KVD, 1.f,
        wqkv + (size_t)DD * DD);
    transpose_h<<<dim3(KVD / 32, DD / 32), dim3(32, 8)>>>(Wv, KVD, 1.f,
        wqkv + (size_t)(DD + KVD) * DD);
    transpose_h<<<dim3(DD / 32, DD / 32), dim3(32, 8)>>>(Wo, DD, 1.f, wot);

    // fused QKV projection (fp16 out)
    gemm_h<true><<<dim3(QKVD / 128, MROWS / 128), 256, GSMEM>>>(
        MROWS, QKVD, xh, wqkv, qkv);

    // V transpose for PV B-fragments
    vtrans<<<dim3(NN / 32, KVD / 32, BB), dim3(32, 8)>>>(qkv, vt);

    // attention
    attn_h<<<dim3(NN / 64, HH, BB), 128, ASMEM>>>(qkv, vt, o);

    // output projection (fp32 out)
    gemm_h<false><<<dim3(DD / 128, MROWS / 128), 256, GSMEM>>>(
        MROWS, DD, o, wot, out);
}

// round 11
// speedup vs baseline: 3.2196x; 1.0314x over previous
#include <cuda_runtime.h>
#include <cuda_fp16.h>
#include <cuda_bf16.h>
#include <cstdint>

// Problem constants
#define BB 2
#define NN 2048
#define DD 1024
#define HH 16
#define HKV 4
#define HD 64
#define REP 4
#define MROWS (BB * NN)      // 4096
#define KVD (HKV * HD)       // 256
#define QKVD (DD + 2 * KVD)  // 1536

// ---------------------------------------------------------------------------
// Scratch (static device globals)
// ---------------------------------------------------------------------------
__device__ __half g_qkv[MROWS * QKVD];   // packed QKV projections (fp16)
__device__ __half g_o[MROWS * DD];       // attention out (fp16)
__device__ __half g_xh[MROWS * DD];      // x in fp16
__device__ __half g_wqkv[QKVD * DD];     // Wq|Wk|Wv transposed [n][k] fp16
__device__ __half g_wot[DD * DD];        // Wo transposed [n][k] fp16

// ---------------------------------------------------------------------------
// Helpers
// ---------------------------------------------------------------------------
__device__ __forceinline__ float ex2(float x) {
    float r;
    asm("ex2.approx.ftz.f32 %0, %1;" : "=f"(r) : "f"(x));
    return r;
}
// D(16x8) += A(16x16) * B(16x8), fp16 in, fp32 acc
__device__ __forceinline__ void mma_h(float* c, const uint32_t* a,
                                      uint32_t b0, uint32_t b1) {
    asm volatile(
        "mma.sync.aligned.m16n8k16.row.col.f32.f16.f16.f32 "
        "{%0,%1,%2,%3}, {%4,%5,%6,%7}, {%8,%9}, {%0,%1,%2,%3};\n"
        : "+f"(c[0]), "+f"(c[1]), "+f"(c[2]), "+f"(c[3])
        : "r"(a[0]), "r"(a[1]), "r"(a[2]), "r"(a[3]), "r"(b0), "r"(b1));
}
__device__ __forceinline__ void ldm4(uint32_t& r0, uint32_t& r1, uint32_t& r2,
                                     uint32_t& r3, uint32_t addr) {
    asm volatile(
        "ldmatrix.sync.aligned.m8n8.x4.shared.b16 {%0,%1,%2,%3}, [%4];"
        : "=r"(r0), "=r"(r1), "=r"(r2), "=r"(r3) : "r"(addr));
}
__device__ __forceinline__ void ldm4t(uint32_t& r0, uint32_t& r1, uint32_t& r2,
                                      uint32_t& r3, uint32_t addr) {
    asm volatile(
        "ldmatrix.sync.aligned.m8n8.x4.trans.shared.b16 {%0,%1,%2,%3}, [%4];"
        : "=r"(r0), "=r"(r1), "=r"(r2), "=r"(r3) : "r"(addr));
}
__device__ __forceinline__ void cp16(uint32_t dst, const void* src) {
    asm volatile("cp.async.ca.shared.global [%0], [%1], 16;"
                 :: "r"(dst), "l"(src));
}
#define CP_COMMIT() asm volatile("cp.async.commit_group;")
#define CP_WAIT(n)  asm volatile("cp.async.wait_group %0;" :: "n"(n))
__device__ __forceinline__ uint32_t smem_u32(const void* p) {
    return (uint32_t)__cvta_generic_to_shared(p);
}

// ---------------------------------------------------------------------------
// Prep kernels
// ---------------------------------------------------------------------------
// fp32 -> fp16 flat convert
__global__ void conv_half(const float* __restrict__ in,
                          __half* __restrict__ out, int n4) {
    int i = blockIdx.x * blockDim.x + threadIdx.x;
    if (i >= n4) return;
    float4 v = ((const float4*)in)[i];
    __half2* o2 = (__half2*)(out + (size_t)i * 4);
    o2[0] = __floats2half2_rn(v.x, v.y);
    o2[1] = __floats2half2_rn(v.z, v.w);
}

// One launch transposes all 4 weights. z selects tensor. src fp32 [1024][C]
// -> dst fp16 [C][1024]. Wq pre-scaled by 1/sqrt(HD)*log2(e).
__global__ void transpose_all(const float* __restrict__ Wq,
                              const float* __restrict__ Wk,
                              const float* __restrict__ Wv,
                              const float* __restrict__ Wo,
                              __half* __restrict__ wqkv,
                              __half* __restrict__ wot) {
    const int z = blockIdx.z;
    const float* src;
    __half* dst;
    int C;
    float scale = 1.f;
    if (z == 0) { src = Wq; dst = wqkv; C = DD;
                  scale = 0.125f * 1.4426950408889634f; }
    else if (z == 1) { src = Wk; dst = wqkv + (size_t)DD * DD; C = KVD; }
    else if (z == 2) { src = Wv; dst = wqkv + (size_t)(DD + KVD) * DD; C = KVD; }
    else { src = Wo; dst = wot; C = DD; }
    const int c0 = blockIdx.x * 32;
    if (c0 >= C) return;
    const int r0 = blockIdx.y * 32;
    __shared__ float t[32][33];
    const int tx = threadIdx.x, ty = threadIdx.y;
#pragma unroll
    for (int i = 0; i < 32; i += 8)
        t[ty + i][tx] = src[(size_t)(r0 + ty + i) * C + c0 + tx];
    __syncthreads();
#pragma unroll
    for (int i = 0; i < 32; i += 8)
        dst[(size_t)(c0 + ty + i) * DD + r0 + tx] =
            __float2half(t[tx][ty + i] * scale);
}

// ---------------------------------------------------------------------------
// fp16 GEMM: C[M,N] = A[M,1024] @ Bt[N,1024]^T. 128x128 CTA tile, 8 warps,
// warp tile 32x64, m16n8k16, ldmatrix feeds, 4-stage cp.async ring,
// ONE syncthreads per stage.
// ---------------------------------------------------------------------------
#define PH 40                  // stage pitch in halves (32 data + 8 pad)
#define STGH (128 * PH)        // halves per operand per stage
#define GSMEM (4 * 2 * STGH * 2)  // 81920 bytes

template <bool HOUT>
__global__ __launch_bounds__(256, 2) void gemm_h(
    int M, int N, const __half* __restrict__ A, const __half* __restrict__ Bt,
    void* __restrict__ Cvoid)
{
    extern __shared__ __half hsm[];
    const uint32_t smb = smem_u32(hsm);

    const int tid  = threadIdx.x;
    const int lane = tid & 31;
    const int w    = tid >> 5;
    const int g    = lane >> 2;
    const int t    = lane & 3;
    const int wm   = (w & 3) * 32;
    const int wn   = (w >> 2) * 64;
    const int bm   = blockIdx.y * 128;
    const int bn   = blockIdx.x * 128;
    const int NS   = 1024 / 32;

    const int arow = (lane & 15);
    const int ach  = (lane >> 4);
    const int brow = (lane & 7) + ((lane >> 4) << 3);
    const int bch  = (lane >> 3) & 1;

    auto issue = [&](int s) {
        const int st = s & 3;
        const uint32_t ua = smb + st * 2 * STGH * 2;
        const uint32_t ub = ua + STGH * 2;
#pragma unroll
        for (int i = 0; i < 2; i++) {
            const int c   = tid + i * 256;   // 512 chunks (128 rows x 4)
            const int row = c >> 2, ch = c & 3;
            cp16(ua + (row * PH + ch * 8) * 2,
                 A + (size_t)(bm + row) * 1024 + s * 32 + ch * 8);
            cp16(ub + (row * PH + ch * 8) * 2,
                 Bt + (size_t)(bn + row) * 1024 + s * 32 + ch * 8);
        }
        CP_COMMIT();
    };

    float acc[2][8][4];
#pragma unroll
    for (int mt = 0; mt < 2; mt++)
#pragma unroll
        for (int nt = 0; nt < 8; nt++)
#pragma unroll
            for (int j = 0; j < 4; j++) acc[mt][nt][j] = 0.f;

    issue(0); issue(1); issue(2);

    for (int s = 0; s < NS; s++) {
        const int st = s & 3;
        const int pend = NS - 1 - s;
        if (pend >= 2)      CP_WAIT(2);
        else if (pend == 1) CP_WAIT(1);
        else                CP_WAIT(0);
        __syncthreads();
        // safe: all warps passed the sync => done computing stage s-1,
        // whose buffer (s+3)&3 == (s-1)&3 is what issue() refills.
        if (s + 3 < NS) issue(s + 3);

        const uint32_t uA = smb + st * 2 * STGH * 2;
        const uint32_t uB = uA + STGH * 2;
#pragma unroll
        for (int kf = 0; kf < 2; kf++) {
            uint32_t a[2][4];
#pragma unroll
            for (int mt = 0; mt < 2; mt++)
                ldm4(a[mt][0], a[mt][1], a[mt][2], a[mt][3],
                     uA + ((wm + mt * 16 + arow) * PH +
                           (2 * kf + ach) * 8) * 2);
#pragma unroll
            for (int nt2 = 0; nt2 < 4; nt2++) {
                uint32_t b0, b1, b2, b3;
                ldm4(b0, b1, b2, b3,
                     uB + ((wn + nt2 * 16 + brow) * PH +
                           (2 * kf + bch) * 8) * 2);
#pragma unroll
                for (int mt = 0; mt < 2; mt++) {
                    mma_h(acc[mt][2 * nt2],     a[mt], b0, b1);
                    mma_h(acc[mt][2 * nt2 + 1], a[mt], b2, b3);
                }
            }
        }
    }

#pragma unroll
    for (int mt = 0; mt < 2; mt++)
#pragma unroll
        for (int nt = 0; nt < 8; nt++) {
            const int row = bm + wm + mt * 16 + g;
            const int col = bn + wn + nt * 8 + 2 * t;
            if (HOUT) {
                __half* C = (__half*)Cvoid;
                *(__half2*)(C + (size_t)row * N + col) =
                    __floats2half2_rn(acc[mt][nt][0], acc[mt][nt][1]);
                *(__half2*)(C + (size_t)(row + 8) * N + col) =
                    __floats2half2_rn(acc[mt][nt][2], acc[mt][nt][3]);
            } else {
                float* C = (float*)Cvoid;
                *(float2*)(C + (size_t)row * N + col) =
                    make_float2(acc[mt][nt][0], acc[mt][nt][1]);
                *(float2*)(C + (size_t)(row + 8) * N + col) =
                    make_float2(acc[mt][nt][2], acc[mt][nt][3]);
            }
        }
}

// ---------------------------------------------------------------------------
// fp16 flash attention. Br=64 (4 warps x 16 rows), Bc=128, m16n8k16.
// K AND V tiles loaded identically from qkv ([kv][hd] rows); V B-fragments
// via ldmatrix.trans (no pre-transpose). One syncthreads per iteration.
// Q pre-scaled by 1/sqrt(HD)*log2(e) (folded into Wq). fp32 softmax/acc.
// ---------------------------------------------------------------------------
#define AP 72                        // K/V pitch: 64 data + 8 pad halves
#define PP 136                       // P pitch: 128 data + 8 pad halves
#define KVTILE (128 * AP)            // 9216 halves per K or V tile
#define NT2 (NN / 128)               // 16 kv tiles
#define ASMEM ((4 * KVTILE + 64 * PP) * 2)   // 91136 bytes

__global__ __launch_bounds__(128, 2) void attn_h(
    const __half* __restrict__ qkv, __half* __restrict__ O)
{
    extern __shared__ __half hsm[];
    const uint32_t smb = smem_u32(hsm);
    const uint32_t uK[2] = { smb, smb + KVTILE * 2 };
    const uint32_t uV[2] = { smb + 2 * KVTILE * 2, smb + 3 * KVTILE * 2 };
    const uint32_t uP    = smb + 4 * KVTILE * 2;
    __half* Ps = hsm + 4 * KVTILE;

    const int tid  = threadIdx.x;
    const int lane = tid & 31;
    const int w    = tid >> 5;
    const int g    = lane >> 2;
    const int t    = lane & 3;
    const int b    = blockIdx.z;
    const int h    = blockIdx.y;
    const int q0   = blockIdx.x * 64;
    const int kvh  = h >> 2;

    const int arow = (lane & 15);
    const int ach  = (lane >> 4);
    const int brow = (lane & 7) + ((lane >> 4) << 3);
    const int bch  = (lane >> 3) & 1;
    // trans-V lane map: row = kv within 16-block, col = hd 8-block
    const int vrow = (lane & 7) + (((lane >> 3) & 1) << 3);
    const int vcol = (lane >> 4) << 3;

    // tiles: 128 rows x 64 halves = 128x8 chunks = 1024 chunks per tensor
    auto issue_tile = [&](int stage, int kt) {
#pragma unroll
        for (int i = 0; i < 8; i++) {
            const int c   = tid + i * 128;
            const int row = c >> 3, ch = c & 7;
            const __half* base =
                qkv + (size_t)(b * NN + kt * 128 + row) * QKVD + kvh * HD + ch * 8;
            cp16(uK[stage] + (row * AP + ch * 8) * 2, base + DD);
            cp16(uV[stage] + (row * AP + ch * 8) * 2, base + DD + KVD);
        }
        CP_COMMIT();
    };

    issue_tile(0, 0);

    // Q fragments (pre-scaled fp16, registers whole kernel)
    uint32_t qa[4][4];
    {
        const __half* qb = qkv + (size_t)(b * NN + q0 + w * 16) * QKVD + h * HD;
#pragma unroll
        for (int kf = 0; kf < 4; kf++) {
            qa[kf][0] = *(const uint32_t*)(qb + (size_t)g * QKVD + kf * 16 + 2 * t);
            qa[kf][1] = *(const uint32_t*)(qb + (size_t)(g + 8) * QKVD + kf * 16 + 2 * t);
            qa[kf][2] = *(const uint32_t*)(qb + (size_t)g * QKVD + kf * 16 + 8 + 2 * t);
            qa[kf][3] = *(const uint32_t*)(qb + (size_t)(g + 8) * QKVD + kf * 16 + 8 + 2 * t);
        }
    }

    float o[8][4];
#pragma unroll
    for (int nt = 0; nt < 8; nt++)
#pragma unroll
        for (int j = 0; j < 4; j++) o[nt][j] = 0.f;
    float m0 = -1e30f, m1 = -1e30f, l0 = 0.f, l1 = 0.f;

    const int prow0 = w * 16 + g, prow1 = prow0 + 8;

    for (int kt = 0; kt < NT2; kt++) {
        const int cur = kt & 1;
        CP_WAIT(0);          // tile kt resident
        __syncthreads();     // everyone done with buffer cur^1 (iter kt-1)
        if (kt + 1 < NT2) issue_tile(cur ^ 1, kt + 1);  // overlaps compute

        // S = Q @ K^T  (16 x 128)
        float s[16][4];
#pragma unroll
        for (int nt = 0; nt < 16; nt++)
#pragma unroll
            for (int j = 0; j < 4; j++) s[nt][j] = 0.f;
#pragma unroll
        for (int kf = 0; kf < 4; kf++) {
#pragma unroll
            for (int nt2 = 0; nt2 < 8; nt2++) {
                uint32_t b0, b1, b2, b3;
                ldm4(b0, b1, b2, b3,
                     uK[cur] + ((nt2 * 16 + brow) * AP +
                                (2 * kf + bch) * 8) * 2);
                mma_h(s[2 * nt2],     qa[kf], b0, b1);
                mma_h(s[2 * nt2 + 1], qa[kf], b2, b3);
            }
        }

        // online softmax (rows g, g+8); S in log2 domain
        float mx0 = -1e30f, mx1 = -1e30f;
#pragma unroll
        for (int nt = 0; nt < 16; nt++) {
            mx0 = fmaxf(mx0, fmaxf(s[nt][0], s[nt][1]));
            mx1 = fmaxf(mx1, fmaxf(s[nt][2], s[nt][3]));
        }
        mx0 = fmaxf(mx0, __shfl_xor_sync(0xffffffffu, mx0, 1));
        mx0 = fmaxf(mx0, __shfl_xor_sync(0xffffffffu, mx0, 2));
        mx1 = fmaxf(mx1, __shfl_xor_sync(0xffffffffu, mx1, 1));
        mx1 = fmaxf(mx1, __shfl_xor_sync(0xffffffffu, mx1, 2));
        const float nm0 = fmaxf(m0, mx0), nm1 = fmaxf(m1, mx1);
        const float cf0 = ex2(m0 - nm0), cf1 = ex2(m1 - nm1);
        m0 = nm0; m1 = nm1;
        l0 *= cf0; l1 *= cf1;
#pragma unroll
        for (int nt = 0; nt < 8; nt++) {
            o[nt][0] *= cf0; o[nt][1] *= cf0;
            o[nt][2] *= cf1; o[nt][3] *= cf1;
        }
        // P = exp2(S - m) -> fp16 -> Ps (half2 stores, conflict-free)
#pragma unroll
        for (int nt = 0; nt < 16; nt++) {
            const float p0 = ex2(s[nt][0] - m0), p1 = ex2(s[nt][1] - m0);
            const float p2 = ex2(s[nt][2] - m1), p3 = ex2(s[nt][3] - m1);
            l0 += p0 + p1;
            l1 += p2 + p3;
            *(__half2*)(Ps + prow0 * PP + nt * 8 + 2 * t) =
                __floats2half2_rn(p0, p1);
            *(__half2*)(Ps + prow1 * PP + nt * 8 + 2 * t) =
                __floats2half2_rn(p2, p3);
        }
        __syncwarp();

        // O += P @ V.  A-frags from Ps; B-frags via ldmatrix.trans on V[kv][hd]
#pragma unroll
        for (int kf = 0; kf < 8; kf++) {
            uint32_t pa[4];
            ldm4(pa[0], pa[1], pa[2], pa[3],
                 uP + ((w * 16 + arow) * PP + (2 * kf + ach) * 8) * 2);
#pragma unroll
            for (int nv = 0; nv < 4; nv++) {
                uint32_t b0, b1, b2, b3;
                ldm4t(b0, b1, b2, b3,
                      uV[cur] + ((kf * 16 + vrow) * AP + nv * 16 + vcol) * 2);
                mma_h(o[2 * nv],     pa, b0, b1);
                mma_h(o[2 * nv + 1], pa, b2, b3);
            }
        }
    }

    l0 += __shfl_xor_sync(0xffffffffu, l0, 1);
    l0 += __shfl_xor_sync(0xffffffffu, l0, 2);
    l1 += __shfl_xor_sync(0xffffffffu, l1, 1);
    l1 += __shfl_xor_sync(0xffffffffu, l1, 2);
    const float inv0 = 1.f / l0, inv1 = 1.f / l1;

    __half* ob = O + (size_t)(b * NN + q0 + w * 16) * DD + h * HD;
#pragma unroll
    for (int nt = 0; nt < 8; nt++) {
        const int col = nt * 8 + 2 * t;
        *(__half2*)(ob + (size_t)g * DD + col) =
            __floats2half2_rn(o[nt][0] * inv0, o[nt][1] * inv0);
        *(__half2*)(ob + (size_t)(g + 8) * DD + col) =
            __floats2half2_rn(o[nt][2] * inv1, o[nt][3] * inv1);
    }
}

// ---------------------------------------------------------------------------
// Launch
// ---------------------------------------------------------------------------
extern "C" void kernel_launch(void* const* d_in, const int* in_sizes, int n_in,
                              void* d_out, int out_size)
{
    const float* x  = (const float*)d_in[0];
    const float* Wq = (const float*)d_in[1];
    const float* Wk = (const float*)d_in[2];
    const float* Wv = (const float*)d_in[3];
    const float* Wo = (const float*)d_in[4];
    float* out = (float*)d_out;

    __half *qkv, *o, *xh, *wqkv, *wot;
    cudaGetSymbolAddress((void**)&qkv,  g_qkv);
    cudaGetSymbolAddress((void**)&o,    g_o);
    cudaGetSymbolAddress((void**)&xh,   g_xh);
    cudaGetSymbolAddress((void**)&wqkv, g_wqkv);
    cudaGetSymbolAddress((void**)&wot,  g_wot);

    cudaFuncSetAttribute(attn_h, cudaFuncAttributeMaxDynamicSharedMemorySize,
                         ASMEM);
    cudaFuncSetAttribute(gemm_h<true>,
                         cudaFuncAttributeMaxDynamicSharedMemorySize, GSMEM);
    cudaFuncSetAttribute(gemm_h<false>,
                         cudaFuncAttributeMaxDynamicSharedMemorySize, GSMEM);

    // prep: x -> fp16; all 4 weights transposed in one launch
    {
        const int n4 = MROWS * DD / 4;
        conv_half<<<(n4 + 255) / 256, 256>>>(x, xh, n4);
    }
    transpose_all<<<dim3(DD / 32, DD / 32, 4), dim3(32, 8)>>>(
        Wq, Wk, Wv, Wo, wqkv, wot);

    // fused QKV projection (fp16 out)
    gemm_h<true><<<dim3(QKVD / 128, MROWS / 128), 256, GSMEM>>>(
        MROWS, QKVD, xh, wqkv, qkv);

    // attention (V transposed in-register via ldmatrix.trans)
    attn_h<<<dim3(NN / 64, HH, BB), 128, ASMEM>>>(qkv, o);

    // output projection (fp32 out)
    gemm_h<false><<<dim3(DD / 128, MROWS / 128), 256, GSMEM>>>(
        MROWS, DD, o, wot, out);
}

// round 12
// speedup vs baseline: 3.4041x; 1.0573x over previous
#include <cuda_runtime.h>
#include <cuda_fp16.h>
#include <cuda_bf16.h>
#include <cstdint>

// Problem constants
#define BB 2
#define NN 2048
#define DD 1024
#define HH 16
#define HKV 4
#define HD 64
#define REP 4
#define MROWS (BB * NN)      // 4096
#define KVD (HKV * HD)       // 256
#define QKVD (DD + 2 * KVD)  // 1536

// ---------------------------------------------------------------------------
// Scratch (static device globals)
// ---------------------------------------------------------------------------
__device__ __half g_qkv[MROWS * QKVD];   // packed QKV projections (fp16)
__device__ __half g_o[MROWS * DD];       // attention out (fp16)
__device__ __half g_xh[MROWS * DD];      // x in fp16
__device__ __half g_wqkv[QKVD * DD];     // Wq|Wk|Wv transposed [n][k] fp16
__device__ __half g_wot[DD * DD];        // Wo transposed [n][k] fp16

// ---------------------------------------------------------------------------
// Helpers
// ---------------------------------------------------------------------------
__device__ __forceinline__ float ex2(float x) {
    float r;
    asm("ex2.approx.ftz.f32 %0, %1;" : "=f"(r) : "f"(x));
    return r;
}
// D(16x8) += A(16x16) * B(16x8), fp16 in, fp32 acc
__device__ __forceinline__ void mma_h(float* c, const uint32_t* a,
                                      uint32_t b0, uint32_t b1) {
    asm volatile(
        "mma.sync.aligned.m16n8k16.row.col.f32.f16.f16.f32 "
        "{%0,%1,%2,%3}, {%4,%5,%6,%7}, {%8,%9}, {%0,%1,%2,%3};\n"
        : "+f"(c[0]), "+f"(c[1]), "+f"(c[2]), "+f"(c[3])
        : "r"(a[0]), "r"(a[1]), "r"(a[2]), "r"(a[3]), "r"(b0), "r"(b1));
}
__device__ __forceinline__ void ldm4(uint32_t& r0, uint32_t& r1, uint32_t& r2,
                                     uint32_t& r3, uint32_t addr) {
    asm volatile(
        "ldmatrix.sync.aligned.m8n8.x4.shared.b16 {%0,%1,%2,%3}, [%4];"
        : "=r"(r0), "=r"(r1), "=r"(r2), "=r"(r3) : "r"(addr));
}
__device__ __forceinline__ void ldm4t(uint32_t& r0, uint32_t& r1, uint32_t& r2,
                                      uint32_t& r3, uint32_t addr) {
    asm volatile(
        "ldmatrix.sync.aligned.m8n8.x4.trans.shared.b16 {%0,%1,%2,%3}, [%4];"
        : "=r"(r0), "=r"(r1), "=r"(r2), "=r"(r3) : "r"(addr));
}
__device__ __forceinline__ void cp16(uint32_t dst, const void* src) {
    asm volatile("cp.async.ca.shared.global [%0], [%1], 16;"
                 :: "r"(dst), "l"(src));
}
#define CP_COMMIT() asm volatile("cp.async.commit_group;")
#define CP_WAIT(n)  asm volatile("cp.async.wait_group %0;" :: "n"(n))
__device__ __forceinline__ uint32_t smem_u32(const void* p) {
    return (uint32_t)__cvta_generic_to_shared(p);
}
__device__ __forceinline__ uint32_t pack_h2(float a, float b) {
    __half2 h = __floats2half2_rn(a, b);
    return *(uint32_t*)&h;
}

// ---------------------------------------------------------------------------
// Prep kernels
// ---------------------------------------------------------------------------
__global__ void conv_half(const float* __restrict__ in,
                          __half* __restrict__ out, int n4) {
    int i = blockIdx.x * blockDim.x + threadIdx.x;
    if (i >= n4) return;
    float4 v = ((const float4*)in)[i];
    __half2* o2 = (__half2*)(out + (size_t)i * 4);
    o2[0] = __floats2half2_rn(v.x, v.y);
    o2[1] = __floats2half2_rn(v.z, v.w);
}

// One launch transposes all 4 weights. z selects tensor. src fp32 [1024][C]
// -> dst fp16 [C][1024]. Wq pre-scaled by 1/sqrt(HD)*log2(e).
__global__ void transpose_all(const float* __restrict__ Wq,
                              const float* __restrict__ Wk,
                              const float* __restrict__ Wv,
                              const float* __restrict__ Wo,
                              __half* __restrict__ wqkv,
                              __half* __restrict__ wot) {
    const int z = blockIdx.z;
    const float* src;
    __half* dst;
    int C;
    float scale = 1.f;
    if (z == 0) { src = Wq; dst = wqkv; C = DD;
                  scale = 0.125f * 1.4426950408889634f; }
    else if (z == 1) { src = Wk; dst = wqkv + (size_t)DD * DD; C = KVD; }
    else if (z == 2) { src = Wv; dst = wqkv + (size_t)(DD + KVD) * DD; C = KVD; }
    else { src = Wo; dst = wot; C = DD; }
    const int c0 = blockIdx.x * 32;
    if (c0 >= C) return;
    const int r0 = blockIdx.y * 32;
    __shared__ float t[32][33];
    const int tx = threadIdx.x, ty = threadIdx.y;
#pragma unroll
    for (int i = 0; i < 32; i += 8)
        t[ty + i][tx] = src[(size_t)(r0 + ty + i) * C + c0 + tx];
    __syncthreads();
#pragma unroll
    for (int i = 0; i < 32; i += 8)
        dst[(size_t)(c0 + ty + i) * DD + r0 + tx] =
            __float2half(t[tx][ty + i] * scale);
}

// ---------------------------------------------------------------------------
// fp16 GEMM: C[M,N] = A[M,1024] @ Bt[N,1024]^T. 128x128 CTA tile, 8 warps,
// warp tile 32x64, m16n8k16, ldmatrix feeds, 4-stage cp.async ring,
// ONE syncthreads per stage. (unchanged, proven)
// ---------------------------------------------------------------------------
#define PH 40
#define STGH (128 * PH)
#define GSMEM (4 * 2 * STGH * 2)  // 81920 bytes

template <bool HOUT>
__global__ __launch_bounds__(256, 2) void gemm_h(
    int M, int N, const __half* __restrict__ A, const __half* __restrict__ Bt,
    void* __restrict__ Cvoid)
{
    extern __shared__ __half hsm[];
    const uint32_t smb = smem_u32(hsm);

    const int tid  = threadIdx.x;
    const int lane = tid & 31;
    const int w    = tid >> 5;
    const int g    = lane >> 2;
    const int t    = lane & 3;
    const int wm   = (w & 3) * 32;
    const int wn   = (w >> 2) * 64;
    const int bm   = blockIdx.y * 128;
    const int bn   = blockIdx.x * 128;
    const int NS   = 1024 / 32;

    const int arow = (lane & 15);
    const int ach  = (lane >> 4);
    const int brow = (lane & 7) + ((lane >> 4) << 3);
    const int bch  = (lane >> 3) & 1;

    auto issue = [&](int s) {
        const int st = s & 3;
        const uint32_t ua = smb + st * 2 * STGH * 2;
        const uint32_t ub = ua + STGH * 2;
#pragma unroll
        for (int i = 0; i < 2; i++) {
            const int c   = tid + i * 256;
            const int row = c >> 2, ch = c & 3;
            cp16(ua + (row * PH + ch * 8) * 2,
                 A + (size_t)(bm + row) * 1024 + s * 32 + ch * 8);
            cp16(ub + (row * PH + ch * 8) * 2,
                 Bt + (size_t)(bn + row) * 1024 + s * 32 + ch * 8);
        }
        CP_COMMIT();
    };

    float acc[2][8][4];
#pragma unroll
    for (int mt = 0; mt < 2; mt++)
#pragma unroll
        for (int nt = 0; nt < 8; nt++)
#pragma unroll
            for (int j = 0; j < 4; j++) acc[mt][nt][j] = 0.f;

    issue(0); issue(1); issue(2);

    for (int s = 0; s < NS; s++) {
        const int st = s & 3;
        const int pend = NS - 1 - s;
        if (pend >= 2)      CP_WAIT(2);
        else if (pend == 1) CP_WAIT(1);
        else                CP_WAIT(0);
        __syncthreads();
        if (s + 3 < NS) issue(s + 3);

        const uint32_t uA = smb + st * 2 * STGH * 2;
        const uint32_t uB = uA + STGH * 2;
#pragma unroll
        for (int kf = 0; kf < 2; kf++) {
            uint32_t a[2][4];
#pragma unroll
            for (int mt = 0; mt < 2; mt++)
                ldm4(a[mt][0], a[mt][1], a[mt][2], a[mt][3],
                     uA + ((wm + mt * 16 + arow) * PH +
                           (2 * kf + ach) * 8) * 2);
#pragma unroll
            for (int nt2 = 0; nt2 < 4; nt2++) {
                uint32_t b0, b1, b2, b3;
                ldm4(b0, b1, b2, b3,
                     uB + ((wn + nt2 * 16 + brow) * PH +
                           (2 * kf + bch) * 8) * 2);
#pragma unroll
                for (int mt = 0; mt < 2; mt++) {
                    mma_h(acc[mt][2 * nt2],     a[mt], b0, b1);
                    mma_h(acc[mt][2 * nt2 + 1], a[mt], b2, b3);
                }
            }
        }
    }

#pragma unroll
    for (int mt = 0; mt < 2; mt++)
#pragma unroll
        for (int nt = 0; nt < 8; nt++) {
            const int row = bm + wm + mt * 16 + g;
            const int col = bn + wn + nt * 8 + 2 * t;
            if (HOUT) {
                __half* C = (__half*)Cvoid;
                *(__half2*)(C + (size_t)row * N + col) =
                    __floats2half2_rn(acc[mt][nt][0], acc[mt][nt][1]);
                *(__half2*)(C + (size_t)(row + 8) * N + col) =
                    __floats2half2_rn(acc[mt][nt][2], acc[mt][nt][3]);
            } else {
                float* C = (float*)Cvoid;
                *(float2*)(C + (size_t)row * N + col) =
                    make_float2(acc[mt][nt][0], acc[mt][nt][1]);
                *(float2*)(C + (size_t)(row + 8) * N + col) =
                    make_float2(acc[mt][nt][2], acc[mt][nt][3]);
            }
        }
}

// ---------------------------------------------------------------------------
// fp16 flash attention. Br=64 (4 warps x 16 rows), Bc=128, m16n8k16.
// P NEVER touches smem: S's C-fragment layout == PV's A-fragment layout
// (a0=P[g][16kf+2t,+1]=s[2kf].c01, a1=s[2kf].c23, a2=s[2kf+1].c01,
//  a3=s[2kf+1].c23). V B-frags via ldmatrix.trans on row-major V tiles.
// ---------------------------------------------------------------------------
#define AP 72                        // K/V pitch: 64 data + 8 pad halves
#define KVTILE (128 * AP)            // halves per K or V tile
#define NT2 (NN / 128)               // 16 kv tiles
#define ASMEM (4 * KVTILE * 2)       // 73728 bytes

__global__ __launch_bounds__(128, 2) void attn_h(
    const __half* __restrict__ qkv, __half* __restrict__ O)
{
    extern __shared__ __half hsm[];
    const uint32_t smb = smem_u32(hsm);
    const uint32_t uK[2] = { smb, smb + KVTILE * 2 };
    const uint32_t uV[2] = { smb + 2 * KVTILE * 2, smb + 3 * KVTILE * 2 };

    const int tid  = threadIdx.x;
    const int lane = tid & 31;
    const int w    = tid >> 5;
    const int g    = lane >> 2;
    const int t    = lane & 3;
    const int b    = blockIdx.z;
    const int h    = blockIdx.y;
    const int q0   = blockIdx.x * 64;
    const int kvh  = h >> 2;

    const int brow = (lane & 7) + ((lane >> 4) << 3);
    const int bch  = (lane >> 3) & 1;
    // trans-V lane map: row = kv within 16-block, col = hd 8-block
    const int vrow = (lane & 7) + (((lane >> 3) & 1) << 3);
    const int vcol = (lane >> 4) << 3;

    // tiles: 128 rows x 64 halves = 1024 16B-chunks per tensor
    auto issue_tile = [&](int stage, int kt) {
#pragma unroll
        for (int i = 0; i < 8; i++) {
            const int c   = tid + i * 128;
            const int row = c >> 3, ch = c & 7;
            const __half* base =
                qkv + (size_t)(b * NN + kt * 128 + row) * QKVD + kvh * HD + ch * 8;
            cp16(uK[stage] + (row * AP + ch * 8) * 2, base + DD);
            cp16(uV[stage] + (row * AP + ch * 8) * 2, base + DD + KVD);
        }
        CP_COMMIT();
    };

    issue_tile(0, 0);

    // Q fragments (pre-scaled fp16, registers whole kernel)
    uint32_t qa[4][4];
    {
        const __half* qb = qkv + (size_t)(b * NN + q0 + w * 16) * QKVD + h * HD;
#pragma unroll
        for (int kf = 0; kf < 4; kf++) {
            qa[kf][0] = *(const uint32_t*)(qb + (size_t)g * QKVD + kf * 16 + 2 * t);
            qa[kf][1] = *(const uint32_t*)(qb + (size_t)(g + 8) * QKVD + kf * 16 + 2 * t);
            qa[kf][2] = *(const uint32_t*)(qb + (size_t)g * QKVD + kf * 16 + 8 + 2 * t);
            qa[kf][3] = *(const uint32_t*)(qb + (size_t)(g + 8) * QKVD + kf * 16 + 8 + 2 * t);
        }
    }

    float o[8][4];
#pragma unroll
    for (int nt = 0; nt < 8; nt++)
#pragma unroll
        for (int j = 0; j < 4; j++) o[nt][j] = 0.f;
    float m0 = -1e30f, m1 = -1e30f, l0 = 0.f, l1 = 0.f;

    for (int kt = 0; kt < NT2; kt++) {
        const int cur = kt & 1;
        CP_WAIT(0);          // tile kt resident
        __syncthreads();     // all warps done reading buffer cur^1
        if (kt + 1 < NT2) issue_tile(cur ^ 1, kt + 1);  // overlaps compute

        // S = Q @ K^T  (16 x 128)
        float s[16][4];
#pragma unroll
        for (int nt = 0; nt < 16; nt++)
#pragma unroll
            for (int j = 0; j < 4; j++) s[nt][j] = 0.f;
#pragma unroll
        for (int kf = 0; kf < 4; kf++) {
#pragma unroll
            for (int nt2 = 0; nt2 < 8; nt2++) {
                uint32_t b0, b1, b2, b3;
                ldm4(b0, b1, b2, b3,
                     uK[cur] + ((nt2 * 16 + brow) * AP +
                                (2 * kf + bch) * 8) * 2);
                mma_h(s[2 * nt2],     qa[kf], b0, b1);
                mma_h(s[2 * nt2 + 1], qa[kf], b2, b3);
            }
        }

        // online softmax (rows g, g+8); S in log2 domain
        float mx0 = -1e30f, mx1 = -1e30f;
#pragma unroll
        for (int nt = 0; nt < 16; nt++) {
            mx0 = fmaxf(mx0, fmaxf(s[nt][0], s[nt][1]));
            mx1 = fmaxf(mx1, fmaxf(s[nt][2], s[nt][3]));
        }
        mx0 = fmaxf(mx0, __shfl_xor_sync(0xffffffffu, mx0, 1));
        mx0 = fmaxf(mx0, __shfl_xor_sync(0xffffffffu, mx0, 2));
        mx1 = fmaxf(mx1, __shfl_xor_sync(0xffffffffu, mx1, 1));
        mx1 = fmaxf(mx1, __shfl_xor_sync(0xffffffffu, mx1, 2));
        const float nm0 = fmaxf(m0, mx0), nm1 = fmaxf(m1, mx1);
        const float cf0 = ex2(m0 - nm0), cf1 = ex2(m1 - nm1);
        m0 = nm0; m1 = nm1;
        l0 *= cf0; l1 *= cf1;
#pragma unroll
        for (int nt = 0; nt < 8; nt++) {
            o[nt][0] *= cf0; o[nt][1] *= cf0;
            o[nt][2] *= cf1; o[nt][3] *= cf1;
        }
        // P = exp2(S - m) packed DIRECTLY into PV A-fragments (registers)
        uint32_t pa[8][4];
#pragma unroll
        for (int nt = 0; nt < 16; nt++) {
            const float p0 = ex2(s[nt][0] - m0), p1 = ex2(s[nt][1] - m0);
            const float p2 = ex2(s[nt][2] - m1), p3 = ex2(s[nt][3] - m1);
            l0 += p0 + p1;
            l1 += p2 + p3;
            const int kf = nt >> 1, hi = (nt & 1) << 1;  // 0 -> a0/a1, 1 -> a2/a3
            pa[kf][hi]     = pack_h2(p0, p1);
            pa[kf][hi + 1] = pack_h2(p2, p3);
        }

        // O += P @ V.  A-frags in registers; B-frags via ldmatrix.trans
#pragma unroll
        for (int kf = 0; kf < 8; kf++) {
#pragma unroll
            for (int nv = 0; nv < 4; nv++) {
                uint32_t b0, b1, b2, b3;
                ldm4t(b0, b1, b2, b3,
                      uV[cur] + ((kf * 16 + vrow) * AP + nv * 16 + vcol) * 2);
                mma_h(o[2 * nv],     pa[kf], b0, b1);
                mma_h(o[2 * nv + 1], pa[kf], b2, b3);
            }
        }
    }

    l0 += __shfl_xor_sync(0xffffffffu, l0, 1);
    l0 += __shfl_xor_sync(0xffffffffu, l0, 2);
    l1 += __shfl_xor_sync(0xffffffffu, l1, 1);
    l1 += __shfl_xor_sync(0xffffffffu, l1, 2);
    const float inv0 = 1.f / l0, inv1 = 1.f / l1;

    __half* ob = O + (size_t)(b * NN + q0 + w * 16) * DD + h * HD;
#pragma unroll
    for (int nt = 0; nt < 8; nt++) {
        const int col = nt * 8 + 2 * t;
        *(__half2*)(ob + (size_t)g * DD + col) =
            __floats2half2_rn(o[nt][0] * inv0, o[nt][1] * inv0);
        *(__half2*)(ob + (size_t)(g + 8) * DD + col) =
            __floats2half2_rn(o[nt][2] * inv1, o[nt][3] * inv1);
    }
}

// ---------------------------------------------------------------------------
// Launch
// ---------------------------------------------------------------------------
extern "C" void kernel_launch(void* const* d_in, const int* in_sizes, int n_in,
                              void* d_out, int out_size)
{
    const float* x  = (const float*)d_in[0];
    const float* Wq = (const float*)d_in[1];
    const float* Wk = (const float*)d_in[2];
    const float* Wv = (const float*)d_in[3];
    const float* Wo = (const float*)d_in[4];
    float* out = (float*)d_out;

    __half *qkv, *o, *xh, *wqkv, *wot;
    cudaGetSymbolAddress((void**)&qkv,  g_qkv);
    cudaGetSymbolAddress((void**)&o,    g_o);
    cudaGetSymbolAddress((void**)&xh,   g_xh);
    cudaGetSymbolAddress((void**)&wqkv, g_wqkv);
    cudaGetSymbolAddress((void**)&wot,  g_wot);

    cudaFuncSetAttribute(attn_h, cudaFuncAttributeMaxDynamicSharedMemorySize,
                         ASMEM);
    cudaFuncSetAttribute(gemm_h<true>,
                         cudaFuncAttributeMaxDynamicSharedMemorySize, GSMEM);
    cudaFuncSetAttribute(gemm_h<false>,
                         cudaFuncAttributeMaxDynamicSharedMemorySize, GSMEM);

    // prep: x -> fp16; all 4 weights transposed in one launch
    {
        const int n4 = MROWS * DD / 4;
        conv_half<<<(n4 + 255) / 256, 256>>>(x, xh, n4);
    }
    transpose_all<<<dim3(DD / 32, DD / 32, 4), dim3(32, 8)>>>(
        Wq, Wk, Wv, Wo, wqkv, wot);

    // fused QKV projection (fp16 out)
    gemm_h<true><<<dim3(QKVD / 128, MROWS / 128), 256, GSMEM>>>(
        MROWS, QKVD, xh, wqkv, qkv);

    // attention (P stays in registers; V transposed via ldmatrix.trans)
    attn_h<<<dim3(NN / 64, HH, BB), 128, ASMEM>>>(qkv, o);

    // output projection (fp32 out)
    gemm_h<false><<<dim3(DD / 128, MROWS / 128), 256, GSMEM>>>(
        MROWS, DD, o, wot, out);
}

// round 13
// speedup vs baseline: 3.5403x; 1.0400x over previous
#include <cuda_runtime.h>
#include <cuda_fp16.h>
#include <cuda_bf16.h>
#include <cstdint>

// Problem constants
#define BB 2
#define NN 2048
#define DD 1024
#define HH 16
#define HKV 4
#define HD 64
#define REP 4
#define MROWS (BB * NN)      // 4096
#define KVD (HKV * HD)       // 256
#define QKVD (DD + 2 * KVD)  // 1536

// ---------------------------------------------------------------------------
// Scratch (static device globals)
// ---------------------------------------------------------------------------
__device__ __half g_qkv[MROWS * QKVD];   // packed QKV projections (fp16)
__device__ __half g_o[MROWS * DD];       // attention out (fp16)
__device__ __half g_xh[MROWS * DD];      // x in fp16
__device__ __half g_wqkv[QKVD * DD];     // Wq|Wk|Wv transposed [n][k] fp16
__device__ __half g_wot[DD * DD];        // Wo transposed [n][k] fp16

// ---------------------------------------------------------------------------
// Helpers
// ---------------------------------------------------------------------------
__device__ __forceinline__ float ex2(float x) {
    float r;
    asm("ex2.approx.ftz.f32 %0, %1;" : "=f"(r) : "f"(x));
    return r;
}
// D(16x8) += A(16x16) * B(16x8), fp16 in, fp32 acc
__device__ __forceinline__ void mma_h(float* c, const uint32_t* a,
                                      uint32_t b0, uint32_t b1) {
    asm volatile(
        "mma.sync.aligned.m16n8k16.row.col.f32.f16.f16.f32 "
        "{%0,%1,%2,%3}, {%4,%5,%6,%7}, {%8,%9}, {%0,%1,%2,%3};\n"
        : "+f"(c[0]), "+f"(c[1]), "+f"(c[2]), "+f"(c[3])
        : "r"(a[0]), "r"(a[1]), "r"(a[2]), "r"(a[3]), "r"(b0), "r"(b1));
}
__device__ __forceinline__ void ldm4(uint32_t& r0, uint32_t& r1, uint32_t& r2,
                                     uint32_t& r3, uint32_t addr) {
    asm volatile(
        "ldmatrix.sync.aligned.m8n8.x4.shared.b16 {%0,%1,%2,%3}, [%4];"
        : "=r"(r0), "=r"(r1), "=r"(r2), "=r"(r3) : "r"(addr));
}
__device__ __forceinline__ void ldm4t(uint32_t& r0, uint32_t& r1, uint32_t& r2,
                                      uint32_t& r3, uint32_t addr) {
    asm volatile(
        "ldmatrix.sync.aligned.m8n8.x4.trans.shared.b16 {%0,%1,%2,%3}, [%4];"
        : "=r"(r0), "=r"(r1), "=r"(r2), "=r"(r3) : "r"(addr));
}
__device__ __forceinline__ void cp16(uint32_t dst, const void* src) {
    asm volatile("cp.async.ca.shared.global [%0], [%1], 16;"
                 :: "r"(dst), "l"(src));
}
#define CP_COMMIT() asm volatile("cp.async.commit_group;")
#define CP_WAIT(n)  asm volatile("cp.async.wait_group %0;" :: "n"(n))
__device__ __forceinline__ uint32_t smem_u32(const void* p) {
    return (uint32_t)__cvta_generic_to_shared(p);
}
__device__ __forceinline__ uint32_t pack_h2(float a, float b) {
    __half2 h = __floats2half2_rn(a, b);
    return *(uint32_t*)&h;
}

// ---------------------------------------------------------------------------
// Prep kernels
// ---------------------------------------------------------------------------
__global__ void conv_half(const float* __restrict__ in,
                          __half* __restrict__ out, int n4) {
    int i = blockIdx.x * blockDim.x + threadIdx.x;
    if (i >= n4) return;
    float4 v = ((const float4*)in)[i];
    __half2* o2 = (__half2*)(out + (size_t)i * 4);
    o2[0] = __floats2half2_rn(v.x, v.y);
    o2[1] = __floats2half2_rn(v.z, v.w);
}

// One launch transposes all 4 weights. z selects tensor. src fp32 [1024][C]
// -> dst fp16 [C][1024]. Wq pre-scaled by 1/sqrt(HD)*log2(e).
__global__ void transpose_all(const float* __restrict__ Wq,
                              const float* __restrict__ Wk,
                              const float* __restrict__ Wv,
                              const float* __restrict__ Wo,
                              __half* __restrict__ wqkv,
                              __half* __restrict__ wot) {
    const int z = blockIdx.z;
    const float* src;
    __half* dst;
    int C;
    float scale = 1.f;
    if (z == 0) { src = Wq; dst = wqkv; C = DD;
                  scale = 0.125f * 1.4426950408889634f; }
    else if (z == 1) { src = Wk; dst = wqkv + (size_t)DD * DD; C = KVD; }
    else if (z == 2) { src = Wv; dst = wqkv + (size_t)(DD + KVD) * DD; C = KVD; }
    else { src = Wo; dst = wot; C = DD; }
    const int c0 = blockIdx.x * 32;
    if (c0 >= C) return;
    const int r0 = blockIdx.y * 32;
    __shared__ float t[32][33];
    const int tx = threadIdx.x, ty = threadIdx.y;
#pragma unroll
    for (int i = 0; i < 32; i += 8)
        t[ty + i][tx] = src[(size_t)(r0 + ty + i) * C + c0 + tx];
    __syncthreads();
#pragma unroll
    for (int i = 0; i < 32; i += 8)
        dst[(size_t)(c0 + ty + i) * DD + r0 + tx] =
            __float2half(t[tx][ty + i] * scale);
}

// ---------------------------------------------------------------------------
// fp16 GEMM (unchanged, proven): C[M,N] = A[M,1024] @ Bt[N,1024]^T.
// 128x128 CTA tile, 8 warps, m16n8k16, ldmatrix, 4-stage cp.async ring.
// ---------------------------------------------------------------------------
#define PH 40
#define STGH (128 * PH)
#define GSMEM (4 * 2 * STGH * 2)  // 81920 bytes

template <bool HOUT>
__global__ __launch_bounds__(256, 2) void gemm_h(
    int M, int N, const __half* __restrict__ A, const __half* __restrict__ Bt,
    void* __restrict__ Cvoid)
{
    extern __shared__ __half hsm[];
    const uint32_t smb = smem_u32(hsm);

    const int tid  = threadIdx.x;
    const int lane = tid & 31;
    const int w    = tid >> 5;
    const int g    = lane >> 2;
    const int t    = lane & 3;
    const int wm   = (w & 3) * 32;
    const int wn   = (w >> 2) * 64;
    const int bm   = blockIdx.y * 128;
    const int bn   = blockIdx.x * 128;
    const int NS   = 1024 / 32;

    const int arow = (lane & 15);
    const int ach  = (lane >> 4);
    const int brow = (lane & 7) + ((lane >> 4) << 3);
    const int bch  = (lane >> 3) & 1;

    auto issue = [&](int s) {
        const int st = s & 3;
        const uint32_t ua = smb + st * 2 * STGH * 2;
        const uint32_t ub = ua + STGH * 2;
#pragma unroll
        for (int i = 0; i < 2; i++) {
            const int c   = tid + i * 256;
            const int row = c >> 2, ch = c & 3;
            cp16(ua + (row * PH + ch * 8) * 2,
                 A + (size_t)(bm + row) * 1024 + s * 32 + ch * 8);
            cp16(ub + (row * PH + ch * 8) * 2,
                 Bt + (size_t)(bn + row) * 1024 + s * 32 + ch * 8);
        }
        CP_COMMIT();
    };

    float acc[2][8][4];
#pragma unroll
    for (int mt = 0; mt < 2; mt++)
#pragma unroll
        for (int nt = 0; nt < 8; nt++)
#pragma unroll
            for (int j = 0; j < 4; j++) acc[mt][nt][j] = 0.f;

    issue(0); issue(1); issue(2);

    for (int s = 0; s < NS; s++) {
        const int st = s & 3;
        const int pend = NS - 1 - s;
        if (pend >= 2)      CP_WAIT(2);
        else if (pend == 1) CP_WAIT(1);
        else                CP_WAIT(0);
        __syncthreads();
        if (s + 3 < NS) issue(s + 3);

        const uint32_t uA = smb + st * 2 * STGH * 2;
        const uint32_t uB = uA + STGH * 2;
#pragma unroll
        for (int kf = 0; kf < 2; kf++) {
            uint32_t a[2][4];
#pragma unroll
            for (int mt = 0; mt < 2; mt++)
                ldm4(a[mt][0], a[mt][1], a[mt][2], a[mt][3],
                     uA + ((wm + mt * 16 + arow) * PH +
                           (2 * kf + ach) * 8) * 2);
#pragma unroll
            for (int nt2 = 0; nt2 < 4; nt2++) {
                uint32_t b0, b1, b2, b3;
                ldm4(b0, b1, b2, b3,
                     uB + ((wn + nt2 * 16 + brow) * PH +
                           (2 * kf + bch) * 8) * 2);
#pragma unroll
                for (int mt = 0; mt < 2; mt++) {
                    mma_h(acc[mt][2 * nt2],     a[mt], b0, b1);
                    mma_h(acc[mt][2 * nt2 + 1], a[mt], b2, b3);
                }
            }
        }
    }

#pragma unroll
    for (int mt = 0; mt < 2; mt++)
#pragma unroll
        for (int nt = 0; nt < 8; nt++) {
            const int row = bm + wm + mt * 16 + g;
            const int col = bn + wn + nt * 8 + 2 * t;
            if (HOUT) {
                __half* C = (__half*)Cvoid;
                *(__half2*)(C + (size_t)row * N + col) =
                    __floats2half2_rn(acc[mt][nt][0], acc[mt][nt][1]);
                *(__half2*)(C + (size_t)(row + 8) * N + col) =
                    __floats2half2_rn(acc[mt][nt][2], acc[mt][nt][3]);
            } else {
                float* C = (float*)Cvoid;
                *(float2*)(C + (size_t)row * N + col) =
                    make_float2(acc[mt][nt][0], acc[mt][nt][1]);
                *(float2*)(C + (size_t)(row + 8) * N + col) =
                    make_float2(acc[mt][nt][2], acc[mt][nt][3]);
            }
        }
}

// ---------------------------------------------------------------------------
// fp16 flash attention. Br=128 (4 warps x 32 q-rows), Bc=64, m16n8k16.
// Each warp: 2 m-tiles of 16 rows -> every K/V ldmatrix fragment feeds 4 MMAs
// (halves smem-pipe traffic vs 16-row warps). P stays in registers
// (S C-frag layout == PV A-frag layout). V via ldmatrix.trans.
// ---------------------------------------------------------------------------
#define AP 72                        // K/V pitch: 64 data + 8 pad halves
#define KVTILE (64 * AP)             // halves per K or V tile (64 kv rows)
#define NT3 (NN / 64)                // 32 kv tiles
#define ASMEM (4 * KVTILE * 2)       // 36864 bytes

__global__ __launch_bounds__(128, 2) void attn_h(
    const __half* __restrict__ qkv, __half* __restrict__ O)
{
    extern __shared__ __half hsm[];
    const uint32_t smb = smem_u32(hsm);
    const uint32_t uK[2] = { smb, smb + KVTILE * 2 };
    const uint32_t uV[2] = { smb + 2 * KVTILE * 2, smb + 3 * KVTILE * 2 };

    const int tid  = threadIdx.x;
    const int lane = tid & 31;
    const int w    = tid >> 5;
    const int g    = lane >> 2;
    const int t    = lane & 3;
    const int b    = blockIdx.z;
    const int h    = blockIdx.y;
    const int q0   = blockIdx.x * 128 + w * 32;   // warp's first q row
    const int kvh  = h >> 2;

    const int brow = (lane & 7) + ((lane >> 4) << 3);
    const int bch  = (lane >> 3) & 1;
    // trans-V lane map: row = kv within 16-block, col = hd 8-block
    const int vrow = (lane & 7) + (((lane >> 3) & 1) << 3);
    const int vcol = (lane >> 4) << 3;

    // tiles: 64 rows x 64 halves = 512 16B-chunks per tensor
    auto issue_tile = [&](int stage, int kt) {
#pragma unroll
        for (int i = 0; i < 4; i++) {
            const int c   = tid + i * 128;
            const int row = c >> 3, ch = c & 7;
            const __half* base =
                qkv + (size_t)(b * NN + kt * 64 + row) * QKVD + kvh * HD + ch * 8;
            cp16(uK[stage] + (row * AP + ch * 8) * 2, base + DD);
            cp16(uV[stage] + (row * AP + ch * 8) * 2, base + DD + KVD);
        }
        CP_COMMIT();
    };

    issue_tile(0, 0);

    // Q fragments for 2 m-tiles (pre-scaled fp16, registers whole kernel)
    uint32_t qa[2][4][4];
#pragma unroll
    for (int mt = 0; mt < 2; mt++) {
        const __half* qb = qkv + (size_t)(b * NN + q0 + mt * 16) * QKVD + h * HD;
#pragma unroll
        for (int kf = 0; kf < 4; kf++) {
            qa[mt][kf][0] = *(const uint32_t*)(qb + (size_t)g * QKVD + kf * 16 + 2 * t);
            qa[mt][kf][1] = *(const uint32_t*)(qb + (size_t)(g + 8) * QKVD + kf * 16 + 2 * t);
            qa[mt][kf][2] = *(const uint32_t*)(qb + (size_t)g * QKVD + kf * 16 + 8 + 2 * t);
            qa[mt][kf][3] = *(const uint32_t*)(qb + (size_t)(g + 8) * QKVD + kf * 16 + 8 + 2 * t);
        }
    }

    float o[2][8][4];
#pragma unroll
    for (int mt = 0; mt < 2; mt++)
#pragma unroll
        for (int nt = 0; nt < 8; nt++)
#pragma unroll
            for (int j = 0; j < 4; j++) o[mt][nt][j] = 0.f;
    float m0[2] = { -1e30f, -1e30f }, m1[2] = { -1e30f, -1e30f };
    float l0[2] = { 0.f, 0.f },       l1[2] = { 0.f, 0.f };

    for (int kt = 0; kt < NT3; kt++) {
        const int cur = kt & 1;
        CP_WAIT(0);          // tile kt resident
        __syncthreads();     // all warps done reading buffer cur^1
        if (kt + 1 < NT3) issue_tile(cur ^ 1, kt + 1);  // overlaps compute

        // S = Q @ K^T  (32 x 64): one K ldmatrix feeds both m-tiles
        float s[2][8][4];
#pragma unroll
        for (int mt = 0; mt < 2; mt++)
#pragma unroll
            for (int nt = 0; nt < 8; nt++)
#pragma unroll
                for (int j = 0; j < 4; j++) s[mt][nt][j] = 0.f;
#pragma unroll
        for (int kf = 0; kf < 4; kf++) {
#pragma unroll
            for (int nt2 = 0; nt2 < 4; nt2++) {
                uint32_t b0, b1, b2, b3;
                ldm4(b0, b1, b2, b3,
                     uK[cur] + ((nt2 * 16 + brow) * AP +
                                (2 * kf + bch) * 8) * 2);
#pragma unroll
                for (int mt = 0; mt < 2; mt++) {
                    mma_h(s[mt][2 * nt2],     qa[mt][kf], b0, b1);
                    mma_h(s[mt][2 * nt2 + 1], qa[mt][kf], b2, b3);
                }
            }
        }

        // online softmax per m-tile (rows g, g+8); S in log2 domain
        uint32_t pa[2][4][4];
#pragma unroll
        for (int mt = 0; mt < 2; mt++) {
            float mx0 = -1e30f, mx1 = -1e30f;
#pragma unroll
            for (int nt = 0; nt < 8; nt++) {
                mx0 = fmaxf(mx0, fmaxf(s[mt][nt][0], s[mt][nt][1]));
                mx1 = fmaxf(mx1, fmaxf(s[mt][nt][2], s[mt][nt][3]));
            }
            mx0 = fmaxf(mx0, __shfl_xor_sync(0xffffffffu, mx0, 1));
            mx0 = fmaxf(mx0, __shfl_xor_sync(0xffffffffu, mx0, 2));
            mx1 = fmaxf(mx1, __shfl_xor_sync(0xffffffffu, mx1, 1));
            mx1 = fmaxf(mx1, __shfl_xor_sync(0xffffffffu, mx1, 2));
            const float nm0 = fmaxf(m0[mt], mx0), nm1 = fmaxf(m1[mt], mx1);
            const float cf0 = ex2(m0[mt] - nm0), cf1 = ex2(m1[mt] - nm1);
            m0[mt] = nm0; m1[mt] = nm1;
            l0[mt] *= cf0; l1[mt] *= cf1;
#pragma unroll
            for (int nt = 0; nt < 8; nt++) {
                o[mt][nt][0] *= cf0; o[mt][nt][1] *= cf0;
                o[mt][nt][2] *= cf1; o[mt][nt][3] *= cf1;
            }
            // P = exp2(S - m) packed directly into PV A-fragments
#pragma unroll
            for (int nt = 0; nt < 8; nt++) {
                const float p0 = ex2(s[mt][nt][0] - nm0);
                const float p1 = ex2(s[mt][nt][1] - nm0);
                const float p2 = ex2(s[mt][nt][2] - nm1);
                const float p3 = ex2(s[mt][nt][3] - nm1);
                l0[mt] += p0 + p1;
                l1[mt] += p2 + p3;
                const int kf = nt >> 1, hi = (nt & 1) << 1;
                pa[mt][kf][hi]     = pack_h2(p0, p1);
                pa[mt][kf][hi + 1] = pack_h2(p2, p3);
            }
        }

        // O += P @ V: one V ldmatrix.trans feeds both m-tiles
#pragma unroll
        for (int kf = 0; kf < 4; kf++) {
#pragma unroll
            for (int nv = 0; nv < 4; nv++) {
                uint32_t b0, b1, b2, b3;
                ldm4t(b0, b1, b2, b3,
                      uV[cur] + ((kf * 16 + vrow) * AP + nv * 16 + vcol) * 2);
#pragma unroll
                for (int mt = 0; mt < 2; mt++) {
                    mma_h(o[mt][2 * nv],     pa[mt][kf], b0, b1);
                    mma_h(o[mt][2 * nv + 1], pa[mt][kf], b2, b3);
                }
            }
        }
    }

    // finalize + store
#pragma unroll
    for (int mt = 0; mt < 2; mt++) {
        float a0 = l0[mt], a1 = l1[mt];
        a0 += __shfl_xor_sync(0xffffffffu, a0, 1);
        a0 += __shfl_xor_sync(0xffffffffu, a0, 2);
        a1 += __shfl_xor_sync(0xffffffffu, a1, 1);
        a1 += __shfl_xor_sync(0xffffffffu, a1, 2);
        const float inv0 = 1.f / a0, inv1 = 1.f / a1;

        __half* ob = O + (size_t)(b * NN + q0 + mt * 16) * DD + h * HD;
#pragma unroll
        for (int nt = 0; nt < 8; nt++) {
            const int col = nt * 8 + 2 * t;
            *(__half2*)(ob + (size_t)g * DD + col) =
                __floats2half2_rn(o[mt][nt][0] * inv0, o[mt][nt][1] * inv0);
            *(__half2*)(ob + (size_t)(g + 8) * DD + col) =
                __floats2half2_rn(o[mt][nt][2] * inv1, o[mt][nt][3] * inv1);
        }
    }
}

// ---------------------------------------------------------------------------
// Launch
// ---------------------------------------------------------------------------
extern "C" void kernel_launch(void* const* d_in, const int* in_sizes, int n_in,
                              void* d_out, int out_size)
{
    const float* x  = (const float*)d_in[0];
    const float* Wq = (const float*)d_in[1];
    const float* Wk = (const float*)d_in[2];
    const float* Wv = (const float*)d_in[3];
    const float* Wo = (const float*)d_in[4];
    float* out = (float*)d_out;

    __half *qkv, *o, *xh, *wqkv, *wot;
    cudaGetSymbolAddress((void**)&qkv,  g_qkv);
    cudaGetSymbolAddress((void**)&o,    g_o);
    cudaGetSymbolAddress((void**)&xh,   g_xh);
    cudaGetSymbolAddress((void**)&wqkv, g_wqkv);
    cudaGetSymbolAddress((void**)&wot,  g_wot);

    cudaFuncSetAttribute(attn_h, cudaFuncAttributeMaxDynamicSharedMemorySize,
                         ASMEM);
    cudaFuncSetAttribute(gemm_h<true>,
                         cudaFuncAttributeMaxDynamicSharedMemorySize, GSMEM);
    cudaFuncSetAttribute(gemm_h<false>,
                         cudaFuncAttributeMaxDynamicSharedMemorySize, GSMEM);

    // prep: x -> fp16; all 4 weights transposed in one launch
    {
        const int n4 = MROWS * DD / 4;
        conv_half<<<(n4 + 255) / 256, 256>>>(x, xh, n4);
    }
    transpose_all<<<dim3(DD / 32, DD / 32, 4), dim3(32, 8)>>>(
        Wq, Wk, Wv, Wo, wqkv, wot);

    // fused QKV projection (fp16 out)
    gemm_h<true><<<dim3(QKVD / 128, MROWS / 128), 256, GSMEM>>>(
        MROWS, QKVD, xh, wqkv, qkv);

    // attention: Br=128 (4 warps x 32 rows), Bc=64
    attn_h<<<dim3(NN / 128, HH, BB), 128, ASMEM>>>(qkv, o);

    // output projection (fp32 out)
    gemm_h<false><<<dim3(DD / 128, MROWS / 128), 256, GSMEM>>>(
        MROWS, DD, o, wot, out);
}